// round 8
// baseline (speedup 1.0000x reference)
#include <cuda_runtime.h>
#include <cuda_fp16.h>
#include <cstdint>

#define NU 50000
#define NI 25000
#define DIMV 128
#define GROWS 16
#define EHMAX 600000
#define ERMAX 1000000
#define CHUNK 1024
#define NCHU 49
#define OSTR 50016

#define UF ((size_t)NU * DIMV)
#define IFl ((size_t)NI * DIMV)

// ------------------- fp32 scratch -------------------
// accc[3UF] | sacc[UF] | iacc[IF] | gate[4UF]
#define O_ACCC ((size_t)0)
#define O_SACC (3 * UF)
#define O_IACC (4 * UF)
#define O_GATE (4 * UF + IFl)
#define TOTALF (8 * UF + IFl)
__device__ __align__(16) float g_buf[TOTALF];

// ------------------- fp16 scratch -------------------
#define H_GATE ((size_t)0)
#define H_CURA (3 * UF)
#define H_MIX  (6 * UF)
#define H_S1   (7 * UF)
#define H_I1   (8 * UF)
#define H_IEMB (8 * UF + IFl)
#define TOTALH (8 * UF + 2 * IFl)
__device__ __align__(16) __half g_hbuf[TOTALH];

__device__ float g_attvec[DIMV];

// ------------------- CSR scratch -------------------
#define CNT_TOT (4 * NU + NI)
#define OFFS_TOT (4 * OSTR + NI + 16)
#define PE_TOT (3 * EHMAX + 2 * ERMAX)
__device__ __align__(16) int g_cnt[CNT_TOT];
__device__ __align__(16) int g_cur[CNT_TOT];
__device__ __align__(16) int g_offs[OFFS_TOT];
__device__ __align__(16) int2 g_pair[PE_TOT];
__device__ int g_aux[5 * 64];

// ------------------- attention vector: v = M @ a -------------------
__global__ void attvec_kernel(const float* __restrict__ att, const float* __restrict__ mat) {
    int j = threadIdx.x;
    float s = 0.f;
#pragma unroll 8
    for (int d = 0; d < DIMV; d++) s += mat[j * DIMV + d] * att[d];
    g_attvec[j] = s;
}

// ------------------- f32 -> f16 conversion -------------------
__global__ void __launch_bounds__(256) f2h_kernel(const float* __restrict__ src,
                                                  __half* __restrict__ dst, int n4) {
    int i = blockIdx.x * 256 + threadIdx.x;
    if (i < n4) {
        float4 v = __ldg((const float4*)src + i);
        union { __half2 h[2]; uint2 u; } cv;
        cv.h[0] = __floats2half2_rn(v.x, v.y);
        cv.h[1] = __floats2half2_rn(v.z, v.w);
        *(uint2*)(dst + (size_t)i * 4) = cv.u;
    }
}

// ------------------- gating with packed f32x2 FFMA -------------------
__device__ __forceinline__ void ffma2(unsigned long long& c, unsigned long long a, unsigned long long b) {
    asm("fma.rn.f32x2 %0, %1, %2, %3;" : "=l"(c) : "l"(a), "l"(b), "l"(c));
}

__global__ void __launch_bounds__(128) gate_kernel(const float* __restrict__ U,
                                                   const float* __restrict__ W4,
                                                   const float* __restrict__ B4,
                                                   float* __restrict__ gate_out,
                                                   __half* __restrict__ gate16) {
    extern __shared__ float sm[];
    float* Wt = sm;
    float* Us = sm + DIMV * 132;
    int t = threadIdx.x;
    int c = blockIdx.y;
    const float* W = W4 + c * DIMV * DIMV;
    float b = B4[c * DIMV + t];
    float* out = gate_out + (size_t)c * UF;
    __half* out16 = (c < 3) ? (gate16 + (size_t)c * UF) : nullptr;
    unsigned long long bp = (unsigned long long)__float_as_uint(b);

    for (int k = 0; k < DIMV; k++) Wt[t * 132 + k] = W[k * DIMV + t];

    for (int r0 = blockIdx.x * GROWS; r0 < NU; r0 += gridDim.x * GROWS) {
        __syncthreads();
#pragma unroll
        for (int r = 0; r < GROWS; r++) Us[r * DIMV + t] = U[(size_t)(r0 + r) * DIMV + t];
        __syncthreads();
        unsigned long long acc2[GROWS];
#pragma unroll
        for (int r = 0; r < GROWS; r++) acc2[r] = bp;
#pragma unroll 4
        for (int k = 0; k < DIMV; k += 4) {
            ulonglong2 w2 = *(const ulonglong2*)&Wt[t * 132 + k];
#pragma unroll
            for (int r = 0; r < GROWS; r++) {
                ulonglong2 u2 = *(const ulonglong2*)&Us[r * DIMV + k];
                ffma2(acc2[r], u2.x, w2.x);
                ffma2(acc2[r], u2.y, w2.y);
            }
        }
#pragma unroll
        for (int r = 0; r < GROWS; r++) {
            float lo = __uint_as_float((unsigned)acc2[r]);
            float hi = __uint_as_float((unsigned)(acc2[r] >> 32));
            float a = lo + hi;
            float uv = Us[r * DIMV + t];
            float g = uv / (1.f + expf(-a));
            out[(size_t)(r0 + r) * DIMV + t] = g;
            if (out16) out16[(size_t)(r0 + r) * DIMV + t] = __float2half_rn(g);
        }
    }
}

// ------------------- CSR build -------------------
struct BuildJob { const int* rows; const int* cols; const float* vals;
                  int* cnt; int* cur; int* offs; int2* pair; int ne; int nrows; };
struct Build5 { BuildJob j[5]; };

__global__ void __launch_bounds__(256) count_kernel(Build5 a) {
    BuildJob jb = a.j[blockIdx.y];
    int e = blockIdx.x * 256 + threadIdx.x;
    if (e < jb.ne) atomicAdd(jb.cnt + __ldg(jb.rows + e), 1);
}

__global__ void __launch_bounds__(256) scan_chunks_kernel(Build5 a, int* __restrict__ aux) {
    BuildJob jb = a.j[blockIdx.y];
    int n = jb.nrows;
    int base = blockIdx.x * CHUNK;
    if (base >= n) return;
    int tid = threadIdx.x;
    int lane = tid & 31, wid = tid >> 5;
    int i = base + tid * 4;
    int4 v = make_int4(0, 0, 0, 0);
    if (i < n) v = *(const int4*)(jb.cnt + i);
    int s = v.x + v.y + v.z + v.w;
    int ss = s;
#pragma unroll
    for (int o = 1; o < 32; o <<= 1) { int tt = __shfl_up_sync(0xffffffffu, ss, o); if (lane >= o) ss += tt; }
    __shared__ int wsum[8];
    if (lane == 31) wsum[wid] = ss;
    __syncthreads();
    if (tid < 8) {
        int w = wsum[tid];
#pragma unroll
        for (int o = 1; o < 8; o <<= 1) { int tt = __shfl_up_sync(0xffu, w, o); if (tid >= o) w += tt; }
        wsum[tid] = w;
    }
    __syncthreads();
    int excl = ss - s + (wid ? wsum[wid - 1] : 0);
    if (i < n) {
        int4 e;
        e.x = excl; e.y = excl + v.x; e.z = e.y + v.y; e.w = e.z + v.z;
        *(int4*)(jb.offs + i) = e;
    }
    if (tid == 255) aux[blockIdx.y * 64 + blockIdx.x] = wsum[7];
}

__global__ void __launch_bounds__(160) scan_aux_kernel(Build5 a, int* __restrict__ aux) {
    int wid = threadIdx.x >> 5;
    if (wid >= 5) return;
    BuildJob jb = a.j[wid];
    int nch = (jb.nrows + CHUNK - 1) / CHUNK;
    int lane = threadIdx.x & 31;
    int carry = 0;
    for (int b0 = 0; b0 < nch; b0 += 32) {
        int idx = b0 + lane;
        int v = (idx < nch) ? aux[wid * 64 + idx] : 0;
        int s = v;
#pragma unroll
        for (int o = 1; o < 32; o <<= 1) { int tt = __shfl_up_sync(0xffffffffu, s, o); if (lane >= o) s += tt; }
        if (idx < nch) aux[wid * 64 + idx] = carry + s - v;
        carry += __shfl_sync(0xffffffffu, s, 31);
    }
    if (lane == 0) jb.offs[jb.nrows] = carry;
}

__global__ void __launch_bounds__(256) scan_apply_kernel(Build5 a, const int* __restrict__ aux) {
    BuildJob jb = a.j[blockIdx.y];
    int n = jb.nrows;
    int base = blockIdx.x * CHUNK;
    if (base >= n) return;
    int add = aux[blockIdx.y * 64 + blockIdx.x];
    int i = base + threadIdx.x * 4;
    if (i < n) {
        int4 e = *(const int4*)(jb.offs + i);
        e.x += add; e.y += add; e.z += add; e.w += add;
        *(int4*)(jb.offs + i) = e;
        *(int4*)(jb.cur + i) = e;
    }
}

__global__ void __launch_bounds__(256) scatter_kernel(Build5 a) {
    BuildJob jb = a.j[blockIdx.y];
    int e = blockIdx.x * 256 + threadIdx.x;
    if (e >= jb.ne) return;
    int r = __ldg(jb.rows + e);
    int p = atomicAdd(jb.cur + r, 1);
    jb.pair[p] = make_int2(__ldg(jb.cols + e), __float_as_int(__ldg(jb.vals + e)));
}

// ------------------- CSR SpMM (fp16 gathers), warp per row, fused epilogues -------------------
struct CsrJob { const int* offs; const int2* pair; const __half* X;
                __half* Y16; float* acc; int nrows; int first; };
struct Csr5 { CsrJob j[5]; };

__device__ __forceinline__ void fma_h(float4& acc, float v, uint2 raw) {
    __half2 h0 = *(__half2*)&raw.x;
    __half2 h1 = *(__half2*)&raw.y;
    float2 f0 = __half22float2(h0);
    float2 f1 = __half22float2(h1);
    acc.x += v * f0.x; acc.y += v * f0.y; acc.z += v * f1.x; acc.w += v * f1.y;
}

__global__ void __launch_bounds__(256) spmm_csr5_kernel(Csr5 a) {
    CsrJob jb = a.j[blockIdx.y];
    int w = (int)((blockIdx.x * (unsigned)blockDim.x + threadIdx.x) >> 5);
    int lane = threadIdx.x & 31;
    if (w >= jb.nrows) return;
    const unsigned FM = 0xffffffffu;
    int start = __ldg(jb.offs + w);
    int end = __ldg(jb.offs + w + 1);
    float4 acc = make_float4(0.f, 0.f, 0.f, 0.f);
    const __half* X = jb.X;
    for (int b = start; b < end; b += 32) {
        int i = b + lane;
        int c = 0; float v = 0.f;
        if (i < end) { int2 pr = __ldg(jb.pair + i); c = pr.x; v = __int_as_float(pr.y); }
        int m = end - b; if (m > 32) m = 32;
        int j = 0;
        for (; j + 4 <= m; j += 4) {
            int c0 = __shfl_sync(FM, c, j + 0);
            int c1 = __shfl_sync(FM, c, j + 1);
            int c2 = __shfl_sync(FM, c, j + 2);
            int c3 = __shfl_sync(FM, c, j + 3);
            uint2 x0 = __ldg((const uint2*)(X + (size_t)c0 * DIMV) + lane);
            uint2 x1 = __ldg((const uint2*)(X + (size_t)c1 * DIMV) + lane);
            uint2 x2 = __ldg((const uint2*)(X + (size_t)c2 * DIMV) + lane);
            uint2 x3 = __ldg((const uint2*)(X + (size_t)c3 * DIMV) + lane);
            float v0 = __shfl_sync(FM, v, j + 0);
            float v1 = __shfl_sync(FM, v, j + 1);
            float v2 = __shfl_sync(FM, v, j + 2);
            float v3 = __shfl_sync(FM, v, j + 3);
            fma_h(acc, v0, x0);
            fma_h(acc, v1, x1);
            fma_h(acc, v2, x2);
            fma_h(acc, v3, x3);
        }
        for (; j < m; j++) {
            int cj = __shfl_sync(FM, c, j);
            float vj = __shfl_sync(FM, v, j);
            uint2 x = __ldg((const uint2*)(X + (size_t)cj * DIMV) + lane);
            fma_h(acc, vj, x);
        }
    }
    size_t base = (size_t)w * DIMV + lane * 4;
    if (jb.Y16) {
        union { __half2 h[2]; uint2 u; } cv;
        cv.h[0] = __floats2half2_rn(acc.x, acc.y);
        cv.h[1] = __floats2half2_rn(acc.z, acc.w);
        *(uint2*)(jb.Y16 + base) = cv.u;
    }
    float ss = acc.x * acc.x + acc.y * acc.y + acc.z * acc.z + acc.w * acc.w;
#pragma unroll
    for (int o = 16; o; o >>= 1) ss += __shfl_xor_sync(FM, ss, o);
    float sc = rsqrtf(fmaxf(ss, 1e-12f));
    if (jb.first) {
        float4 a;
        a.x = acc.x * sc; a.y = acc.y * sc; a.z = acc.z * sc; a.w = acc.w * sc;
        *(float4*)(jb.acc + base) = a;
    } else {
        float4 a = *(const float4*)(jb.acc + base);
        a.x += acc.x * sc; a.y += acc.y * sc; a.z += acc.z * sc; a.w += acc.w * sc;
        *(float4*)(jb.acc + base) = a;
    }
}

// ------------------- mix (fp32 inputs) -------------------
__global__ void __launch_bounds__(256) mix_kernel(
        const float* __restrict__ C0, const float* __restrict__ C1, const float* __restrict__ C2,
        const float* __restrict__ A0, const float* __restrict__ A1, const float* __restrict__ A2,
        const float* __restrict__ S, const float* __restrict__ S2,
        float* __restrict__ out32, __half* __restrict__ out16, int nrows) {
    int w = (int)((blockIdx.x * (unsigned)blockDim.x + threadIdx.x) >> 5);
    int lane = threadIdx.x & 31;
    if (w >= nrows) return;
    size_t base = (size_t)w * DIMV + lane * 4;
    float4 v = *(const float4*)(g_attvec + lane * 4);
    float4 c0 = *(const float4*)(C0 + base);
    float4 c1 = *(const float4*)(C1 + base);
    float4 c2 = *(const float4*)(C2 + base);
    if (A0) {
        float4 a0 = *(const float4*)(A0 + base);
        float4 a1 = *(const float4*)(A1 + base);
        float4 a2 = *(const float4*)(A2 + base);
        c0.x += a0.x; c0.y += a0.y; c0.z += a0.z; c0.w += a0.w;
        c1.x += a1.x; c1.y += a1.y; c1.z += a1.z; c1.w += a1.w;
        c2.x += a2.x; c2.y += a2.y; c2.z += a2.z; c2.w += a2.w;
    }
    float w0 = c0.x * v.x + c0.y * v.y + c0.z * v.z + c0.w * v.w;
    float w1 = c1.x * v.x + c1.y * v.y + c1.z * v.z + c1.w * v.w;
    float w2 = c2.x * v.x + c2.y * v.y + c2.z * v.z + c2.w * v.w;
#pragma unroll
    for (int o = 16; o; o >>= 1) {
        w0 += __shfl_xor_sync(0xffffffffu, w0, o);
        w1 += __shfl_xor_sync(0xffffffffu, w1, o);
        w2 += __shfl_xor_sync(0xffffffffu, w2, o);
    }
    float m = fmaxf(w0, fmaxf(w1, w2));
    float e0 = expf(w0 - m), e1 = expf(w1 - m), e2 = expf(w2 - m);
    float inv = 1.f / (e0 + e1 + e2);
    e0 *= inv; e1 *= inv; e2 *= inv;
    float4 s = *(const float4*)(S + base);
    if (S2) {
        float4 s2 = *(const float4*)(S2 + base);
        s.x += s2.x; s.y += s2.y; s.z += s2.z; s.w += s2.w;
    }
    float4 o;
    o.x = e0 * c0.x + e1 * c1.x + e2 * c2.x + 0.5f * s.x;
    o.y = e0 * c0.y + e1 * c1.y + e2 * c2.y + 0.5f * s.y;
    o.z = e0 * c0.z + e1 * c1.z + e2 * c2.z + 0.5f * s.z;
    o.w = e0 * c0.w + e1 * c1.w + e2 * c2.w + 0.5f * s.w;
    if (out32) *(float4*)(out32 + base) = o;
    if (out16) {
        union { __half2 h[2]; uint2 u; } cv;
        cv.h[0] = __floats2half2_rn(o.x, o.y);
        cv.h[1] = __floats2half2_rn(o.z, o.w);
        *(uint2*)(out16 + base) = cv.u;
    }
}

// ------------------- mix (fp16 inputs) -------------------
__device__ __forceinline__ float4 ldh4(const __half* p) {
    uint2 r = *(const uint2*)p;
    float2 f0 = __half22float2(*(__half2*)&r.x);
    float2 f1 = __half22float2(*(__half2*)&r.y);
    return make_float4(f0.x, f0.y, f1.x, f1.y);
}

__global__ void __launch_bounds__(256) mix_h_kernel(
        const __half* __restrict__ C0, const __half* __restrict__ C1, const __half* __restrict__ C2,
        const __half* __restrict__ S, __half* __restrict__ out16, int nrows) {
    int w = (int)((blockIdx.x * (unsigned)blockDim.x + threadIdx.x) >> 5);
    int lane = threadIdx.x & 31;
    if (w >= nrows) return;
    size_t base = (size_t)w * DIMV + lane * 4;
    float4 v = *(const float4*)(g_attvec + lane * 4);
    float4 c0 = ldh4(C0 + base);
    float4 c1 = ldh4(C1 + base);
    float4 c2 = ldh4(C2 + base);
    float w0 = c0.x * v.x + c0.y * v.y + c0.z * v.z + c0.w * v.w;
    float w1 = c1.x * v.x + c1.y * v.y + c1.z * v.z + c1.w * v.w;
    float w2 = c2.x * v.x + c2.y * v.y + c2.z * v.z + c2.w * v.w;
#pragma unroll
    for (int o = 16; o; o >>= 1) {
        w0 += __shfl_xor_sync(0xffffffffu, w0, o);
        w1 += __shfl_xor_sync(0xffffffffu, w1, o);
        w2 += __shfl_xor_sync(0xffffffffu, w2, o);
    }
    float m = fmaxf(w0, fmaxf(w1, w2));
    float e0 = expf(w0 - m), e1 = expf(w1 - m), e2 = expf(w2 - m);
    float inv = 1.f / (e0 + e1 + e2);
    e0 *= inv; e1 *= inv; e2 *= inv;
    float4 s = ldh4(S + base);
    float4 o;
    o.x = e0 * c0.x + e1 * c1.x + e2 * c2.x + 0.5f * s.x;
    o.y = e0 * c0.y + e1 * c1.y + e2 * c2.y + 0.5f * s.y;
    o.z = e0 * c0.z + e1 * c1.z + e2 * c2.z + 0.5f * s.z;
    o.w = e0 * c0.w + e1 * c1.w + e2 * c2.w + 0.5f * s.w;
    union { __half2 h[2]; uint2 u; } cv;
    cv.h[0] = __floats2half2_rn(o.x, o.y);
    cv.h[1] = __floats2half2_rn(o.z, o.w);
    *(uint2*)(out16 + base) = cv.u;
}

// ------------------- item output -------------------
__global__ void __launch_bounds__(256) item_out_kernel(const float* __restrict__ ie,
                                                       const float* __restrict__ ia,
                                                       float* __restrict__ out) {
    int i = blockIdx.x * blockDim.x + threadIdx.x;
    if (i < (int)(IFl / 4)) {
        float4 a = __ldg((const float4*)ie + i);
        float4 b = *((const float4*)ia + i);
        a.x += b.x; a.y += b.y; a.z += b.z; a.w += b.w;
        *((float4*)out + i) = a;
    }
}

// ------------------- host orchestration -------------------
extern "C" void kernel_launch(void* const* d_in, const int* in_sizes, int n_in,
                              void* d_out, int out_size) {
    const float* u_emb = (const float*)d_in[0];
    const float* i_emb = (const float*)d_in[1];
    const float* gW = (const float*)d_in[2];
    const float* gB = (const float*)d_in[3];
    const float* att = (const float*)d_in[4];
    const float* attm = (const float*)d_in[5];
    const int* Hr[3] = {(const int*)d_in[6], (const int*)d_in[9], (const int*)d_in[12]};
    const int* Hc[3] = {(const int*)d_in[7], (const int*)d_in[10], (const int*)d_in[13]};
    const float* Hv[3] = {(const float*)d_in[8], (const float*)d_in[11], (const float*)d_in[14]};
    const int* Rr = (const int*)d_in[15];
    const int* Rc = (const int*)d_in[16];
    const float* Rv = (const float*)d_in[17];
    int EH = in_sizes[6], ER = in_sizes[15];
    float* out = (float*)d_out;

    static float* B = nullptr;
    static __half* H = nullptr;
    static int *cnt = nullptr, *cur = nullptr, *offs = nullptr, *aux = nullptr;
    static int2* pair = nullptr;
    static size_t smem = (size_t)(DIMV * 132 + GROWS * DIMV) * sizeof(float);
    if (!B) {
        cudaGetSymbolAddress((void**)&B, g_buf);
        cudaGetSymbolAddress((void**)&H, g_hbuf);
        cudaGetSymbolAddress((void**)&cnt, g_cnt);
        cudaGetSymbolAddress((void**)&cur, g_cur);
        cudaGetSymbolAddress((void**)&offs, g_offs);
        cudaGetSymbolAddress((void**)&pair, g_pair);
        cudaGetSymbolAddress((void**)&aux, g_aux);
        cudaFuncSetAttribute(gate_kernel, cudaFuncAttributeMaxDynamicSharedMemorySize, (int)smem);
    }
    float* accc = B + O_ACCC;
    float* sacc = B + O_SACC;
    float* iacc = B + O_IACC;
    float* gate = B + O_GATE;
    __half* gate16 = H + H_GATE;
    __half* curA16 = H + H_CURA;
    __half* mix16 = H + H_MIX;
    __half* s1_16 = H + H_S1;
    __half* i1_16 = H + H_I1;
    __half* iemb16 = H + H_IEMB;

#define GP(c) (gate + (size_t)(c) * UF)
#define GP16(c) (gate16 + (size_t)(c) * UF)
#define CA16(c) (curA16 + (size_t)(c) * UF)
#define AC(c) (accc + (size_t)(c) * UF)

    Build5 bj;
    for (int k = 0; k < 3; k++)
        bj.j[k] = {Hr[k], Hc[k], Hv[k], cnt + k * NU, cur + k * NU, offs + k * OSTR,
                   pair + (size_t)k * EHMAX, EH, NU};
    bj.j[3] = {Rr, Rc, Rv, cnt + 3 * NU, cur + 3 * NU, offs + 3 * OSTR,
               pair + 3 * (size_t)EHMAX, ER, NU};
    bj.j[4] = {Rc, Rr, Rv, cnt + 4 * NU, cur + 4 * NU, offs + 4 * OSTR,
               pair + 3 * (size_t)EHMAX + ERMAX, ER, NI};

    const int* offsR = bj.j[3].offs;  const int2* pairR = bj.j[3].pair;
    const int* offsRT = bj.j[4].offs; const int2* pairRT = bj.j[4].pair;

    cudaMemsetAsync(cnt, 0, CNT_TOT * sizeof(int));

    attvec_kernel<<<1, 128>>>(att, attm);
    f2h_kernel<<<(int)((IFl / 4 + 255) / 256), 256>>>(i_emb, iemb16, (int)(IFl / 4));
    gate_kernel<<<dim3(448, 4), 128, smem>>>(u_emb, gW, gB, gate, gate16);

    int maxE = EH > ER ? EH : ER;
    count_kernel<<<dim3((maxE + 255) / 256, 5), 256>>>(bj);
    scan_chunks_kernel<<<dim3(NCHU, 5), 256>>>(bj, aux);
    scan_aux_kernel<<<1, 160>>>(bj, aux);
    scan_apply_kernel<<<dim3(NCHU, 5), 256>>>(bj, aux);
    scatter_kernel<<<dim3((maxE + 255) / 256, 5), 256>>>(bj);

    int mixb = (NU + 7) / 8;
    int rowbU = (NU + 7) / 8;

    mix_kernel<<<mixb, 256>>>(GP(0), GP(1), GP(2), nullptr, nullptr, nullptr,
                              GP(3), nullptr, nullptr, mix16, NU);

    // ---------------- layer 1: 5 fused jobs (all acc first-write) ----------------
    {
        Csr5 a;
        for (int k = 0; k < 3; k++)
            a.j[k] = {bj.j[k].offs, bj.j[k].pair, GP16(k), CA16(k), AC(k), NU, 1};
        a.j[3] = {offsRT, pairRT, mix16, i1_16, iacc, NI, 1};    // item1 = R^T @ mixed
        a.j[4] = {offsR, pairR, iemb16, s1_16, sacc, NU, 1};     // s1 = R @ i_emb
        spmm_csr5_kernel<<<dim3(rowbU, 5), 256>>>(a);
    }

    // ---------------- layer 2 ----------------
    mix_h_kernel<<<mixb, 256>>>(CA16(0), CA16(1), CA16(2), s1_16, mix16, NU);
    {
        Csr5 a;
        for (int k = 0; k < 3; k++)
            a.j[k] = {bj.j[k].offs, bj.j[k].pair, CA16(k), nullptr, AC(k), NU, 0};
        a.j[3] = {offsRT, pairRT, mix16, nullptr, iacc, NI, 0};  // l2n(R^T @ mixed2)
        a.j[4] = {offsR, pairR, i1_16, nullptr, sacc, NU, 0};    // l2n(R @ item1)
        spmm_csr5_kernel<<<dim3(rowbU, 5), 256>>>(a);
    }

    // ---------------- final ----------------
    mix_kernel<<<mixb, 256>>>(GP(0), GP(1), GP(2), AC(0), AC(1), AC(2),
                              GP(3), sacc, out, nullptr, NU);
    item_out_kernel<<<(int)((IFl / 4 + 255) / 256), 256>>>(i_emb, iacc, out + (size_t)NU * DIMV);
}

// round 9
// speedup vs baseline: 1.4186x; 1.4186x over previous
#include <cuda_runtime.h>
#include <cuda_fp16.h>
#include <cstdint>

#define NU 50000
#define NI 25000
#define DIMV 128
#define GROWS 16
#define EHMAX 600000
#define ERMAX 1000000
#define CHUNK 1024
#define NCHU 49
#define OSTR 50016

#define UF ((size_t)NU * DIMV)
#define IFl ((size_t)NI * DIMV)

// ------------------- fp32 scratch -------------------
// accc[3UF] | sacc[UF] | iacc[IF] | gate[4UF]
#define O_ACCC ((size_t)0)
#define O_SACC (3 * UF)
#define O_IACC (4 * UF)
#define O_GATE (4 * UF + IFl)
#define TOTALF (8 * UF + IFl)
__device__ __align__(16) float g_buf[TOTALF];

// ------------------- fp16 scratch -------------------
#define H_GATE ((size_t)0)
#define H_CURA (3 * UF)
#define H_MIX  (6 * UF)
#define H_S1   (7 * UF)
#define H_I1   (8 * UF)
#define H_IEMB (8 * UF + IFl)
#define TOTALH (8 * UF + 2 * IFl)
__device__ __align__(16) __half g_hbuf[TOTALH];

__device__ float g_attvec[DIMV];

// ------------------- CSR scratch -------------------
#define CNT_TOT (4 * NU + NI)
#define OFFS_TOT (4 * OSTR + NI + 16)
#define PE_TOT (3 * EHMAX + 2 * ERMAX)
__device__ __align__(16) int g_cnt[CNT_TOT];
__device__ __align__(16) int g_cur[CNT_TOT];
__device__ __align__(16) int g_offs[OFFS_TOT];
__device__ __align__(16) int2 g_pair[PE_TOT];
__device__ int g_aux[5 * 64];

// ------------------- attention vector: v = M @ a -------------------
__global__ void attvec_kernel(const float* __restrict__ att, const float* __restrict__ mat) {
    int j = threadIdx.x;
    float s = 0.f;
#pragma unroll 8
    for (int d = 0; d < DIMV; d++) s += mat[j * DIMV + d] * att[d];
    g_attvec[j] = s;
}

// ------------------- f32 -> f16 conversion -------------------
__global__ void __launch_bounds__(256) f2h_kernel(const float* __restrict__ src,
                                                  __half* __restrict__ dst, int n4) {
    int i = blockIdx.x * 256 + threadIdx.x;
    if (i < n4) {
        float4 v = __ldg((const float4*)src + i);
        union { __half2 h[2]; uint2 u; } cv;
        cv.h[0] = __floats2half2_rn(v.x, v.y);
        cv.h[1] = __floats2half2_rn(v.z, v.w);
        *(uint2*)(dst + (size_t)i * 4) = cv.u;
    }
}

// ------------------- gating with packed f32x2 FFMA -------------------
__device__ __forceinline__ void ffma2(unsigned long long& c, unsigned long long a, unsigned long long b) {
    asm("fma.rn.f32x2 %0, %1, %2, %3;" : "=l"(c) : "l"(a), "l"(b), "l"(c));
}

__global__ void __launch_bounds__(128) gate_kernel(const float* __restrict__ U,
                                                   const float* __restrict__ W4,
                                                   const float* __restrict__ B4,
                                                   float* __restrict__ gate_out,
                                                   __half* __restrict__ gate16) {
    extern __shared__ float sm[];
    float* Wt = sm;
    float* Us = sm + DIMV * 132;
    int t = threadIdx.x;
    int c = blockIdx.y;
    const float* W = W4 + c * DIMV * DIMV;
    float b = B4[c * DIMV + t];
    float* out = gate_out + (size_t)c * UF;
    __half* out16 = (c < 3) ? (gate16 + (size_t)c * UF) : nullptr;
    unsigned long long bp = (unsigned long long)__float_as_uint(b);

    for (int k = 0; k < DIMV; k++) Wt[t * 132 + k] = W[k * DIMV + t];

    for (int r0 = blockIdx.x * GROWS; r0 < NU; r0 += gridDim.x * GROWS) {
        __syncthreads();
#pragma unroll
        for (int r = 0; r < GROWS; r++) Us[r * DIMV + t] = U[(size_t)(r0 + r) * DIMV + t];
        __syncthreads();
        unsigned long long acc2[GROWS];
#pragma unroll
        for (int r = 0; r < GROWS; r++) acc2[r] = bp;
#pragma unroll 4
        for (int k = 0; k < DIMV; k += 4) {
            ulonglong2 w2 = *(const ulonglong2*)&Wt[t * 132 + k];
#pragma unroll
            for (int r = 0; r < GROWS; r++) {
                ulonglong2 u2 = *(const ulonglong2*)&Us[r * DIMV + k];
                ffma2(acc2[r], u2.x, w2.x);
                ffma2(acc2[r], u2.y, w2.y);
            }
        }
#pragma unroll
        for (int r = 0; r < GROWS; r++) {
            float lo = __uint_as_float((unsigned)acc2[r]);
            float hi = __uint_as_float((unsigned)(acc2[r] >> 32));
            float a = lo + hi;
            float uv = Us[r * DIMV + t];
            float g = uv / (1.f + expf(-a));
            out[(size_t)(r0 + r) * DIMV + t] = g;
            if (out16) out16[(size_t)(r0 + r) * DIMV + t] = __float2half_rn(g);
        }
    }
}

// ------------------- CSR build -------------------
struct BuildJob { const int* rows; const int* cols; const float* vals;
                  int* cnt; int* cur; int* offs; int2* pair; int ne; int nrows; };
struct Build5 { BuildJob j[5]; };

__global__ void __launch_bounds__(256) count_kernel(Build5 a) {
    BuildJob jb = a.j[blockIdx.y];
    int e = blockIdx.x * 256 + threadIdx.x;
    if (e < jb.ne) atomicAdd(jb.cnt + __ldg(jb.rows + e), 1);
}

__global__ void __launch_bounds__(256) scan_chunks_kernel(Build5 a, int* __restrict__ aux) {
    BuildJob jb = a.j[blockIdx.y];
    int n = jb.nrows;
    int base = blockIdx.x * CHUNK;
    if (base >= n) return;
    int tid = threadIdx.x;
    int lane = tid & 31, wid = tid >> 5;
    int i = base + tid * 4;
    int4 v = make_int4(0, 0, 0, 0);
    if (i < n) v = *(const int4*)(jb.cnt + i);
    int s = v.x + v.y + v.z + v.w;
    int ss = s;
#pragma unroll
    for (int o = 1; o < 32; o <<= 1) { int tt = __shfl_up_sync(0xffffffffu, ss, o); if (lane >= o) ss += tt; }
    __shared__ int wsum[8];
    if (lane == 31) wsum[wid] = ss;
    __syncthreads();
    if (tid < 8) {
        int w = wsum[tid];
#pragma unroll
        for (int o = 1; o < 8; o <<= 1) { int tt = __shfl_up_sync(0xffu, w, o); if (tid >= o) w += tt; }
        wsum[tid] = w;
    }
    __syncthreads();
    int excl = ss - s + (wid ? wsum[wid - 1] : 0);
    if (i < n) {
        int4 e;
        e.x = excl; e.y = excl + v.x; e.z = e.y + v.y; e.w = e.z + v.z;
        *(int4*)(jb.offs + i) = e;
    }
    if (tid == 255) aux[blockIdx.y * 64 + blockIdx.x] = wsum[7];
}

__global__ void __launch_bounds__(160) scan_aux_kernel(Build5 a, int* __restrict__ aux) {
    int wid = threadIdx.x >> 5;
    if (wid >= 5) return;
    BuildJob jb = a.j[wid];
    int nch = (jb.nrows + CHUNK - 1) / CHUNK;
    int lane = threadIdx.x & 31;
    int carry = 0;
    for (int b0 = 0; b0 < nch; b0 += 32) {
        int idx = b0 + lane;
        int v = (idx < nch) ? aux[wid * 64 + idx] : 0;
        int s = v;
#pragma unroll
        for (int o = 1; o < 32; o <<= 1) { int tt = __shfl_up_sync(0xffffffffu, s, o); if (lane >= o) s += tt; }
        if (idx < nch) aux[wid * 64 + idx] = carry + s - v;
        carry += __shfl_sync(0xffffffffu, s, 31);
    }
    if (lane == 0) jb.offs[jb.nrows] = carry;
}

__global__ void __launch_bounds__(256) scan_apply_kernel(Build5 a, const int* __restrict__ aux) {
    BuildJob jb = a.j[blockIdx.y];
    int n = jb.nrows;
    int base = blockIdx.x * CHUNK;
    if (base >= n) return;
    int add = aux[blockIdx.y * 64 + blockIdx.x];
    int i = base + threadIdx.x * 4;
    if (i < n) {
        int4 e = *(const int4*)(jb.offs + i);
        e.x += add; e.y += add; e.z += add; e.w += add;
        *(int4*)(jb.offs + i) = e;
        *(int4*)(jb.cur + i) = e;
    }
}

__global__ void __launch_bounds__(256) scatter_kernel(Build5 a) {
    BuildJob jb = a.j[blockIdx.y];
    int e = blockIdx.x * 256 + threadIdx.x;
    if (e >= jb.ne) return;
    int r = __ldg(jb.rows + e);
    int p = atomicAdd(jb.cur + r, 1);
    jb.pair[p] = make_int2(__ldg(jb.cols + e), __float_as_int(__ldg(jb.vals + e)));
}

// ------------------- CSR SpMM (fp16 gathers), balanced 1D grid, fused epilogues -------------------
struct CsrJob { const int* offs; const int2* pair; const __half* X;
                __half* Y16; float* acc; int nrows; int first; };
struct Csr5 { CsrJob j[5]; int bstart[6]; };

__device__ __forceinline__ void fma_h(float4& acc, float v, uint2 raw) {
    __half2 h0 = *(__half2*)&raw.x;
    __half2 h1 = *(__half2*)&raw.y;
    float2 f0 = __half22float2(h0);
    float2 f1 = __half22float2(h1);
    acc.x += v * f0.x; acc.y += v * f0.y; acc.z += v * f1.x; acc.w += v * f1.y;
}

__global__ void __launch_bounds__(256) spmm_csr5_kernel(Csr5 a) {
    int blk = blockIdx.x;
    int k = 0;
#pragma unroll
    for (int q = 1; q < 5; q++) if (blk >= a.bstart[q]) k = q;
    CsrJob jb = a.j[k];
    int w = (blk - a.bstart[k]) * 8 + (threadIdx.x >> 5);
    int lane = threadIdx.x & 31;
    if (w >= jb.nrows) return;
    const unsigned FM = 0xffffffffu;
    int start = __ldg(jb.offs + w);
    int end = __ldg(jb.offs + w + 1);
    float4 acc = make_float4(0.f, 0.f, 0.f, 0.f);
    const __half* X = jb.X;
    for (int b = start; b < end; b += 32) {
        int i = b + lane;
        int c = 0; float v = 0.f;
        if (i < end) { int2 pr = __ldg(jb.pair + i); c = pr.x; v = __int_as_float(pr.y); }
        int m = end - b; if (m > 32) m = 32;
        int j = 0;
        for (; j + 4 <= m; j += 4) {
            int c0 = __shfl_sync(FM, c, j + 0);
            int c1 = __shfl_sync(FM, c, j + 1);
            int c2 = __shfl_sync(FM, c, j + 2);
            int c3 = __shfl_sync(FM, c, j + 3);
            uint2 x0 = __ldg((const uint2*)(X + (size_t)c0 * DIMV) + lane);
            uint2 x1 = __ldg((const uint2*)(X + (size_t)c1 * DIMV) + lane);
            uint2 x2 = __ldg((const uint2*)(X + (size_t)c2 * DIMV) + lane);
            uint2 x3 = __ldg((const uint2*)(X + (size_t)c3 * DIMV) + lane);
            float v0 = __shfl_sync(FM, v, j + 0);
            float v1 = __shfl_sync(FM, v, j + 1);
            float v2 = __shfl_sync(FM, v, j + 2);
            float v3 = __shfl_sync(FM, v, j + 3);
            fma_h(acc, v0, x0);
            fma_h(acc, v1, x1);
            fma_h(acc, v2, x2);
            fma_h(acc, v3, x3);
        }
        for (; j < m; j++) {
            int cj = __shfl_sync(FM, c, j);
            float vj = __shfl_sync(FM, v, j);
            uint2 x = __ldg((const uint2*)(X + (size_t)cj * DIMV) + lane);
            fma_h(acc, vj, x);
        }
    }
    size_t base = (size_t)w * DIMV + lane * 4;
    if (jb.Y16) {
        union { __half2 h[2]; uint2 u; } cv;
        cv.h[0] = __floats2half2_rn(acc.x, acc.y);
        cv.h[1] = __floats2half2_rn(acc.z, acc.w);
        *(uint2*)(jb.Y16 + base) = cv.u;
    }
    float ss = acc.x * acc.x + acc.y * acc.y + acc.z * acc.z + acc.w * acc.w;
#pragma unroll
    for (int o = 16; o; o >>= 1) ss += __shfl_xor_sync(FM, ss, o);
    float sc = rsqrtf(fmaxf(ss, 1e-12f));
    if (jb.first) {
        float4 a4;
        a4.x = acc.x * sc; a4.y = acc.y * sc; a4.z = acc.z * sc; a4.w = acc.w * sc;
        *(float4*)(jb.acc + base) = a4;
    } else {
        float4 a4 = *(const float4*)(jb.acc + base);
        a4.x += acc.x * sc; a4.y += acc.y * sc; a4.z += acc.z * sc; a4.w += acc.w * sc;
        *(float4*)(jb.acc + base) = a4;
    }
}

// ------------------- mix (fp32 inputs) -------------------
__global__ void __launch_bounds__(256) mix_kernel(
        const float* __restrict__ C0, const float* __restrict__ C1, const float* __restrict__ C2,
        const float* __restrict__ A0, const float* __restrict__ A1, const float* __restrict__ A2,
        const float* __restrict__ S, const float* __restrict__ S2,
        float* __restrict__ out32, __half* __restrict__ out16, int nrows) {
    int w = (int)((blockIdx.x * (unsigned)blockDim.x + threadIdx.x) >> 5);
    int lane = threadIdx.x & 31;
    if (w >= nrows) return;
    size_t base = (size_t)w * DIMV + lane * 4;
    float4 v = *(const float4*)(g_attvec + lane * 4);
    float4 c0 = *(const float4*)(C0 + base);
    float4 c1 = *(const float4*)(C1 + base);
    float4 c2 = *(const float4*)(C2 + base);
    if (A0) {
        float4 a0 = *(const float4*)(A0 + base);
        float4 a1 = *(const float4*)(A1 + base);
        float4 a2 = *(const float4*)(A2 + base);
        c0.x += a0.x; c0.y += a0.y; c0.z += a0.z; c0.w += a0.w;
        c1.x += a1.x; c1.y += a1.y; c1.z += a1.z; c1.w += a1.w;
        c2.x += a2.x; c2.y += a2.y; c2.z += a2.z; c2.w += a2.w;
    }
    float w0 = c0.x * v.x + c0.y * v.y + c0.z * v.z + c0.w * v.w;
    float w1 = c1.x * v.x + c1.y * v.y + c1.z * v.z + c1.w * v.w;
    float w2 = c2.x * v.x + c2.y * v.y + c2.z * v.z + c2.w * v.w;
#pragma unroll
    for (int o = 16; o; o >>= 1) {
        w0 += __shfl_xor_sync(0xffffffffu, w0, o);
        w1 += __shfl_xor_sync(0xffffffffu, w1, o);
        w2 += __shfl_xor_sync(0xffffffffu, w2, o);
    }
    float m = fmaxf(w0, fmaxf(w1, w2));
    float e0 = expf(w0 - m), e1 = expf(w1 - m), e2 = expf(w2 - m);
    float inv = 1.f / (e0 + e1 + e2);
    e0 *= inv; e1 *= inv; e2 *= inv;
    float4 s = *(const float4*)(S + base);
    if (S2) {
        float4 s2 = *(const float4*)(S2 + base);
        s.x += s2.x; s.y += s2.y; s.z += s2.z; s.w += s2.w;
    }
    float4 o;
    o.x = e0 * c0.x + e1 * c1.x + e2 * c2.x + 0.5f * s.x;
    o.y = e0 * c0.y + e1 * c1.y + e2 * c2.y + 0.5f * s.y;
    o.z = e0 * c0.z + e1 * c1.z + e2 * c2.z + 0.5f * s.z;
    o.w = e0 * c0.w + e1 * c1.w + e2 * c2.w + 0.5f * s.w;
    if (out32) *(float4*)(out32 + base) = o;
    if (out16) {
        union { __half2 h[2]; uint2 u; } cv;
        cv.h[0] = __floats2half2_rn(o.x, o.y);
        cv.h[1] = __floats2half2_rn(o.z, o.w);
        *(uint2*)(out16 + base) = cv.u;
    }
}

// ------------------- mix (fp16 inputs) -------------------
__device__ __forceinline__ float4 ldh4(const __half* p) {
    uint2 r = *(const uint2*)p;
    float2 f0 = __half22float2(*(__half2*)&r.x);
    float2 f1 = __half22float2(*(__half2*)&r.y);
    return make_float4(f0.x, f0.y, f1.x, f1.y);
}

__global__ void __launch_bounds__(256) mix_h_kernel(
        const __half* __restrict__ C0, const __half* __restrict__ C1, const __half* __restrict__ C2,
        const __half* __restrict__ S, __half* __restrict__ out16, int nrows) {
    int w = (int)((blockIdx.x * (unsigned)blockDim.x + threadIdx.x) >> 5);
    int lane = threadIdx.x & 31;
    if (w >= nrows) return;
    size_t base = (size_t)w * DIMV + lane * 4;
    float4 v = *(const float4*)(g_attvec + lane * 4);
    float4 c0 = ldh4(C0 + base);
    float4 c1 = ldh4(C1 + base);
    float4 c2 = ldh4(C2 + base);
    float w0 = c0.x * v.x + c0.y * v.y + c0.z * v.z + c0.w * v.w;
    float w1 = c1.x * v.x + c1.y * v.y + c1.z * v.z + c1.w * v.w;
    float w2 = c2.x * v.x + c2.y * v.y + c2.z * v.z + c2.w * v.w;
#pragma unroll
    for (int o = 16; o; o >>= 1) {
        w0 += __shfl_xor_sync(0xffffffffu, w0, o);
        w1 += __shfl_xor_sync(0xffffffffu, w1, o);
        w2 += __shfl_xor_sync(0xffffffffu, w2, o);
    }
    float m = fmaxf(w0, fmaxf(w1, w2));
    float e0 = expf(w0 - m), e1 = expf(w1 - m), e2 = expf(w2 - m);
    float inv = 1.f / (e0 + e1 + e2);
    e0 *= inv; e1 *= inv; e2 *= inv;
    float4 s = ldh4(S + base);
    float4 o;
    o.x = e0 * c0.x + e1 * c1.x + e2 * c2.x + 0.5f * s.x;
    o.y = e0 * c0.y + e1 * c1.y + e2 * c2.y + 0.5f * s.y;
    o.z = e0 * c0.z + e1 * c1.z + e2 * c2.z + 0.5f * s.z;
    o.w = e0 * c0.w + e1 * c1.w + e2 * c2.w + 0.5f * s.w;
    union { __half2 h[2]; uint2 u; } cv;
    cv.h[0] = __floats2half2_rn(o.x, o.y);
    cv.h[1] = __floats2half2_rn(o.z, o.w);
    *(uint2*)(out16 + base) = cv.u;
}

// ------------------- item output -------------------
__global__ void __launch_bounds__(256) item_out_kernel(const float* __restrict__ ie,
                                                       const float* __restrict__ ia,
                                                       float* __restrict__ out) {
    int i = blockIdx.x * blockDim.x + threadIdx.x;
    if (i < (int)(IFl / 4)) {
        float4 a = __ldg((const float4*)ie + i);
        float4 b = *((const float4*)ia + i);
        a.x += b.x; a.y += b.y; a.z += b.z; a.w += b.w;
        *((float4*)out + i) = a;
    }
}

// ------------------- host orchestration -------------------
extern "C" void kernel_launch(void* const* d_in, const int* in_sizes, int n_in,
                              void* d_out, int out_size) {
    const float* u_emb = (const float*)d_in[0];
    const float* i_emb = (const float*)d_in[1];
    const float* gW = (const float*)d_in[2];
    const float* gB = (const float*)d_in[3];
    const float* att = (const float*)d_in[4];
    const float* attm = (const float*)d_in[5];
    const int* Hr[3] = {(const int*)d_in[6], (const int*)d_in[9], (const int*)d_in[12]};
    const int* Hc[3] = {(const int*)d_in[7], (const int*)d_in[10], (const int*)d_in[13]};
    const float* Hv[3] = {(const float*)d_in[8], (const float*)d_in[11], (const float*)d_in[14]};
    const int* Rr = (const int*)d_in[15];
    const int* Rc = (const int*)d_in[16];
    const float* Rv = (const float*)d_in[17];
    int EH = in_sizes[6], ER = in_sizes[15];
    float* out = (float*)d_out;

    static float* B = nullptr;
    static __half* H = nullptr;
    static int *cnt = nullptr, *cur = nullptr, *offs = nullptr, *aux = nullptr;
    static int2* pair = nullptr;
    static size_t smem = (size_t)(DIMV * 132 + GROWS * DIMV) * sizeof(float);
    if (!B) {
        cudaGetSymbolAddress((void**)&B, g_buf);
        cudaGetSymbolAddress((void**)&H, g_hbuf);
        cudaGetSymbolAddress((void**)&cnt, g_cnt);
        cudaGetSymbolAddress((void**)&cur, g_cur);
        cudaGetSymbolAddress((void**)&offs, g_offs);
        cudaGetSymbolAddress((void**)&pair, g_pair);
        cudaGetSymbolAddress((void**)&aux, g_aux);
        cudaFuncSetAttribute(gate_kernel, cudaFuncAttributeMaxDynamicSharedMemorySize, (int)smem);
    }
    float* accc = B + O_ACCC;
    float* sacc = B + O_SACC;
    float* iacc = B + O_IACC;
    float* gate = B + O_GATE;
    __half* gate16 = H + H_GATE;
    __half* curA16 = H + H_CURA;
    __half* mix16 = H + H_MIX;
    __half* s1_16 = H + H_S1;
    __half* i1_16 = H + H_I1;
    __half* iemb16 = H + H_IEMB;

#define GP(c) (gate + (size_t)(c) * UF)
#define GP16(c) (gate16 + (size_t)(c) * UF)
#define CA16(c) (curA16 + (size_t)(c) * UF)
#define AC(c) (accc + (size_t)(c) * UF)

    Build5 bj;
    for (int k = 0; k < 3; k++)
        bj.j[k] = {Hr[k], Hc[k], Hv[k], cnt + k * NU, cur + k * NU, offs + k * OSTR,
                   pair + (size_t)k * EHMAX, EH, NU};
    bj.j[3] = {Rr, Rc, Rv, cnt + 3 * NU, cur + 3 * NU, offs + 3 * OSTR,
               pair + 3 * (size_t)EHMAX, ER, NU};
    bj.j[4] = {Rc, Rr, Rv, cnt + 4 * NU, cur + 4 * NU, offs + 4 * OSTR,
               pair + 3 * (size_t)EHMAX + ERMAX, ER, NI};

    const int* offsR = bj.j[3].offs;  const int2* pairR = bj.j[3].pair;
    const int* offsRT = bj.j[4].offs; const int2* pairRT = bj.j[4].pair;

    cudaMemsetAsync(cnt, 0, CNT_TOT * sizeof(int));

    attvec_kernel<<<1, 128>>>(att, attm);
    f2h_kernel<<<(int)((IFl / 4 + 255) / 256), 256>>>(i_emb, iemb16, (int)(IFl / 4));
    gate_kernel<<<dim3(448, 4), 128, smem>>>(u_emb, gW, gB, gate, gate16);

    int maxE = EH > ER ? EH : ER;
    count_kernel<<<dim3((maxE + 255) / 256, 5), 256>>>(bj);
    scan_chunks_kernel<<<dim3(NCHU, 5), 256>>>(bj, aux);
    scan_aux_kernel<<<1, 160>>>(bj, aux);
    scan_apply_kernel<<<dim3(NCHU, 5), 256>>>(bj, aux);
    scatter_kernel<<<dim3((maxE + 255) / 256, 5), 256>>>(bj);

    int mixb = (NU + 7) / 8;
    const int BU = (NU + 7) / 8;   // 6250 blocks for NU-row job
    const int BI = (NI + 7) / 8;   // 3125 blocks for NI-row job

    mix_kernel<<<mixb, 256>>>(GP(0), GP(1), GP(2), nullptr, nullptr, nullptr,
                              GP(3), nullptr, nullptr, mix16, NU);

    // ---------------- layer 1: 5 balanced jobs (all acc first-write) ----------------
    {
        Csr5 a;
        for (int k = 0; k < 3; k++)
            a.j[k] = {bj.j[k].offs, bj.j[k].pair, GP16(k), CA16(k), AC(k), NU, 1};
        a.j[3] = {offsRT, pairRT, mix16, i1_16, iacc, NI, 1};    // item1 = R^T @ mixed
        a.j[4] = {offsR, pairR, iemb16, s1_16, sacc, NU, 1};     // s1 = R @ i_emb
        a.bstart[0] = 0; a.bstart[1] = BU; a.bstart[2] = 2 * BU; a.bstart[3] = 3 * BU;
        a.bstart[4] = 3 * BU + BI; a.bstart[5] = 4 * BU + BI;
        spmm_csr5_kernel<<<a.bstart[5], 256>>>(a);
    }

    // ---------------- layer 2 ----------------
    mix_h_kernel<<<mixb, 256>>>(CA16(0), CA16(1), CA16(2), s1_16, mix16, NU);
    {
        Csr5 a;
        for (int k = 0; k < 3; k++)
            a.j[k] = {bj.j[k].offs, bj.j[k].pair, CA16(k), nullptr, AC(k), NU, 0};
        a.j[3] = {offsRT, pairRT, mix16, nullptr, iacc, NI, 0};  // l2n(R^T @ mixed2)
        a.j[4] = {offsR, pairR, i1_16, nullptr, sacc, NU, 0};    // l2n(R @ item1)
        a.bstart[0] = 0; a.bstart[1] = BU; a.bstart[2] = 2 * BU; a.bstart[3] = 3 * BU;
        a.bstart[4] = 3 * BU + BI; a.bstart[5] = 4 * BU + BI;
        spmm_csr5_kernel<<<a.bstart[5], 256>>>(a);
    }

    // ---------------- final ----------------
    mix_kernel<<<mixb, 256>>>(GP(0), GP(1), GP(2), AC(0), AC(1), AC(2),
                              GP(3), sacc, out, nullptr, NU);
    item_out_kernel<<<(int)((IFl / 4 + 255) / 256), 256>>>(i_emb, iacc, out + (size_t)NU * DIMV);
}

// round 10
// speedup vs baseline: 1.4502x; 1.0223x over previous
#include <cuda_runtime.h>
#include <cuda_fp16.h>
#include <cstdint>

#define NU 50000
#define NI 25000
#define DIMV 128
#define GROWS 16
#define EHMAX 600000
#define ERMAX 1000000
#define CHUNK 1024
#define NCHU 49
#define OSTR 50016

#define UF ((size_t)NU * DIMV)
#define IFl ((size_t)NI * DIMV)

// ------------------- fp32 scratch -------------------
// accc[3UF] | sacc[UF] | iacc[IF] | gate[4UF]
#define O_ACCC ((size_t)0)
#define O_SACC (3 * UF)
#define O_IACC (4 * UF)
#define O_GATE (4 * UF + IFl)
#define TOTALF (8 * UF + IFl)
__device__ __align__(16) float g_buf[TOTALF];

// ------------------- fp16 scratch -------------------
#define H_GATE ((size_t)0)
#define H_CURA (3 * UF)
#define H_MIX  (6 * UF)
#define H_S1   (7 * UF)
#define H_I1   (8 * UF)
#define H_IEMB (8 * UF + IFl)
#define TOTALH (8 * UF + 2 * IFl)
__device__ __align__(16) __half g_hbuf[TOTALH];

__device__ float g_attvec[DIMV];

// ------------------- CSR scratch -------------------
#define CNT_TOT (4 * NU + NI)
#define OFFS_TOT (4 * OSTR + NI + 16)
#define PE_TOT (3 * EHMAX + 2 * ERMAX)
__device__ __align__(16) int g_cnt[CNT_TOT];
__device__ __align__(16) int g_cur[CNT_TOT];
__device__ __align__(16) int g_offs[OFFS_TOT];
__device__ __align__(16) int2 g_pair[PE_TOT];
__device__ int g_aux[5 * 64];

// ------------------- attention vector: v = M @ a -------------------
__global__ void attvec_kernel(const float* __restrict__ att, const float* __restrict__ mat) {
    int j = threadIdx.x;
    float s = 0.f;
#pragma unroll 8
    for (int d = 0; d < DIMV; d++) s += mat[j * DIMV + d] * att[d];
    g_attvec[j] = s;
}

// ------------------- f32 -> f16 conversion -------------------
__global__ void __launch_bounds__(256) f2h_kernel(const float* __restrict__ src,
                                                  __half* __restrict__ dst, int n4) {
    int i = blockIdx.x * 256 + threadIdx.x;
    if (i < n4) {
        float4 v = __ldg((const float4*)src + i);
        union { __half2 h[2]; uint2 u; } cv;
        cv.h[0] = __floats2half2_rn(v.x, v.y);
        cv.h[1] = __floats2half2_rn(v.z, v.w);
        *(uint2*)(dst + (size_t)i * 4) = cv.u;
    }
}

// ------------------- gating with packed f32x2 FFMA -------------------
__device__ __forceinline__ void ffma2(unsigned long long& c, unsigned long long a, unsigned long long b) {
    asm("fma.rn.f32x2 %0, %1, %2, %3;" : "=l"(c) : "l"(a), "l"(b), "l"(c));
}

__global__ void __launch_bounds__(128) gate_kernel(const float* __restrict__ U,
                                                   const float* __restrict__ W4,
                                                   const float* __restrict__ B4,
                                                   float* __restrict__ gate_out,
                                                   __half* __restrict__ gate16) {
    extern __shared__ float sm[];
    float* Wt = sm;
    float* Us = sm + DIMV * 132;
    int t = threadIdx.x;
    int c = blockIdx.y;
    const float* W = W4 + c * DIMV * DIMV;
    float b = B4[c * DIMV + t];
    float* out = gate_out + (size_t)c * UF;
    __half* out16 = (c < 3) ? (gate16 + (size_t)c * UF) : nullptr;
    unsigned long long bp = (unsigned long long)__float_as_uint(b);

    for (int k = 0; k < DIMV; k++) Wt[t * 132 + k] = W[k * DIMV + t];

    for (int r0 = blockIdx.x * GROWS; r0 < NU; r0 += gridDim.x * GROWS) {
        __syncthreads();
#pragma unroll
        for (int r = 0; r < GROWS; r++) Us[r * DIMV + t] = U[(size_t)(r0 + r) * DIMV + t];
        __syncthreads();
        unsigned long long acc2[GROWS];
#pragma unroll
        for (int r = 0; r < GROWS; r++) acc2[r] = bp;
#pragma unroll 4
        for (int k = 0; k < DIMV; k += 4) {
            ulonglong2 w2 = *(const ulonglong2*)&Wt[t * 132 + k];
#pragma unroll
            for (int r = 0; r < GROWS; r++) {
                ulonglong2 u2 = *(const ulonglong2*)&Us[r * DIMV + k];
                ffma2(acc2[r], u2.x, w2.x);
                ffma2(acc2[r], u2.y, w2.y);
            }
        }
#pragma unroll
        for (int r = 0; r < GROWS; r++) {
            float lo = __uint_as_float((unsigned)acc2[r]);
            float hi = __uint_as_float((unsigned)(acc2[r] >> 32));
            float a = lo + hi;
            float uv = Us[r * DIMV + t];
            float g = uv / (1.f + expf(-a));
            out[(size_t)(r0 + r) * DIMV + t] = g;
            if (out16) out16[(size_t)(r0 + r) * DIMV + t] = __float2half_rn(g);
        }
    }
}

// ------------------- CSR build -------------------
struct BuildJob { const int* rows; const int* cols; const float* vals;
                  int* cnt; int* cur; int* offs; int2* pair; int ne; int nrows; };
struct Build5 { BuildJob j[5]; int bstart[6]; };

__device__ __forceinline__ int build_job_of(const Build5& a, int blk) {
    int k = 0;
#pragma unroll
    for (int q = 1; q < 5; q++) if (blk >= a.bstart[q]) k = q;
    return k;
}

__global__ void __launch_bounds__(256) count_kernel(Build5 a) {
    int k = build_job_of(a, blockIdx.x);
    BuildJob jb = a.j[k];
    int e = (blockIdx.x - a.bstart[k]) * 256 + threadIdx.x;
    if (e < jb.ne) atomicAdd(jb.cnt + __ldg(jb.rows + e), 1);
}

__global__ void __launch_bounds__(256) scan_chunks_kernel(Build5 a, int* __restrict__ aux) {
    BuildJob jb = a.j[blockIdx.y];
    int n = jb.nrows;
    int base = blockIdx.x * CHUNK;
    if (base >= n) return;
    int tid = threadIdx.x;
    int lane = tid & 31, wid = tid >> 5;
    int i = base + tid * 4;
    int4 v = make_int4(0, 0, 0, 0);
    if (i < n) v = *(const int4*)(jb.cnt + i);
    int s = v.x + v.y + v.z + v.w;
    int ss = s;
#pragma unroll
    for (int o = 1; o < 32; o <<= 1) { int tt = __shfl_up_sync(0xffffffffu, ss, o); if (lane >= o) ss += tt; }
    __shared__ int wsum[8];
    if (lane == 31) wsum[wid] = ss;
    __syncthreads();
    if (tid < 8) {
        int w = wsum[tid];
#pragma unroll
        for (int o = 1; o < 8; o <<= 1) { int tt = __shfl_up_sync(0xffu, w, o); if (tid >= o) w += tt; }
        wsum[tid] = w;
    }
    __syncthreads();
    int excl = ss - s + (wid ? wsum[wid - 1] : 0);
    if (i < n) {
        int4 e;
        e.x = excl; e.y = excl + v.x; e.z = e.y + v.y; e.w = e.z + v.z;
        *(int4*)(jb.offs + i) = e;
    }
    if (tid == 255) aux[blockIdx.y * 64 + blockIdx.x] = wsum[7];
}

__global__ void __launch_bounds__(160) scan_aux_kernel(Build5 a, int* __restrict__ aux) {
    int wid = threadIdx.x >> 5;
    if (wid >= 5) return;
    BuildJob jb = a.j[wid];
    int nch = (jb.nrows + CHUNK - 1) / CHUNK;
    int lane = threadIdx.x & 31;
    int carry = 0;
    for (int b0 = 0; b0 < nch; b0 += 32) {
        int idx = b0 + lane;
        int v = (idx < nch) ? aux[wid * 64 + idx] : 0;
        int s = v;
#pragma unroll
        for (int o = 1; o < 32; o <<= 1) { int tt = __shfl_up_sync(0xffffffffu, s, o); if (lane >= o) s += tt; }
        if (idx < nch) aux[wid * 64 + idx] = carry + s - v;
        carry += __shfl_sync(0xffffffffu, s, 31);
    }
    if (lane == 0) jb.offs[jb.nrows] = carry;
}

__global__ void __launch_bounds__(256) scan_apply_kernel(Build5 a, const int* __restrict__ aux) {
    BuildJob jb = a.j[blockIdx.y];
    int n = jb.nrows;
    int base = blockIdx.x * CHUNK;
    if (base >= n) return;
    int add = aux[blockIdx.y * 64 + blockIdx.x];
    int i = base + threadIdx.x * 4;
    if (i < n) {
        int4 e = *(const int4*)(jb.offs + i);
        e.x += add; e.y += add; e.z += add; e.w += add;
        *(int4*)(jb.offs + i) = e;
        *(int4*)(jb.cur + i) = e;
    }
}

__global__ void __launch_bounds__(256) scatter_kernel(Build5 a) {
    int k = build_job_of(a, blockIdx.x);
    BuildJob jb = a.j[k];
    int e = (blockIdx.x - a.bstart[k]) * 256 + threadIdx.x;
    if (e >= jb.ne) return;
    int r = __ldg(jb.rows + e);
    int p = atomicAdd(jb.cur + r, 1);
    jb.pair[p] = make_int2(__ldg(jb.cols + e), __float_as_int(__ldg(jb.vals + e)));
}

// ------------------- CSR SpMM (fp16 gathers), balanced 1D grid, fused epilogues -------------------
struct CsrJob { const int* offs; const int2* pair; const __half* X;
                __half* Y16; float* acc; int nrows; int first; };
struct Csr5 { CsrJob j[5]; int bstart[6]; };

__device__ __forceinline__ void fma_h(float4& acc, float v, uint2 raw) {
    __half2 h0 = *(__half2*)&raw.x;
    __half2 h1 = *(__half2*)&raw.y;
    float2 f0 = __half22float2(h0);
    float2 f1 = __half22float2(h1);
    acc.x += v * f0.x; acc.y += v * f0.y; acc.z += v * f1.x; acc.w += v * f1.y;
}

__global__ void __launch_bounds__(256) spmm_csr5_kernel(Csr5 a) {
    int blk = blockIdx.x;
    int k = 0;
#pragma unroll
    for (int q = 1; q < 5; q++) if (blk >= a.bstart[q]) k = q;
    CsrJob jb = a.j[k];
    int w = (blk - a.bstart[k]) * 8 + (threadIdx.x >> 5);
    int lane = threadIdx.x & 31;
    if (w >= jb.nrows) return;
    const unsigned FM = 0xffffffffu;
    int start = __ldg(jb.offs + w);
    int end = __ldg(jb.offs + w + 1);
    float4 acc = make_float4(0.f, 0.f, 0.f, 0.f);
    const __half* X = jb.X;
    for (int b = start; b < end; b += 32) {
        int i = b + lane;
        int c = 0; float v = 0.f;
        if (i < end) { int2 pr = __ldg(jb.pair + i); c = pr.x; v = __int_as_float(pr.y); }
        int m = end - b; if (m > 32) m = 32;
        int j = 0;
        for (; j + 4 <= m; j += 4) {
            int c0 = __shfl_sync(FM, c, j + 0);
            int c1 = __shfl_sync(FM, c, j + 1);
            int c2 = __shfl_sync(FM, c, j + 2);
            int c3 = __shfl_sync(FM, c, j + 3);
            uint2 x0 = __ldg((const uint2*)(X + (size_t)c0 * DIMV) + lane);
            uint2 x1 = __ldg((const uint2*)(X + (size_t)c1 * DIMV) + lane);
            uint2 x2 = __ldg((const uint2*)(X + (size_t)c2 * DIMV) + lane);
            uint2 x3 = __ldg((const uint2*)(X + (size_t)c3 * DIMV) + lane);
            float v0 = __shfl_sync(FM, v, j + 0);
            float v1 = __shfl_sync(FM, v, j + 1);
            float v2 = __shfl_sync(FM, v, j + 2);
            float v3 = __shfl_sync(FM, v, j + 3);
            fma_h(acc, v0, x0);
            fma_h(acc, v1, x1);
            fma_h(acc, v2, x2);
            fma_h(acc, v3, x3);
        }
        for (; j < m; j++) {
            int cj = __shfl_sync(FM, c, j);
            float vj = __shfl_sync(FM, v, j);
            uint2 x = __ldg((const uint2*)(X + (size_t)cj * DIMV) + lane);
            fma_h(acc, vj, x);
        }
    }
    size_t base = (size_t)w * DIMV + lane * 4;
    if (jb.Y16) {
        union { __half2 h[2]; uint2 u; } cv;
        cv.h[0] = __floats2half2_rn(acc.x, acc.y);
        cv.h[1] = __floats2half2_rn(acc.z, acc.w);
        *(uint2*)(jb.Y16 + base) = cv.u;
    }
    float ss = acc.x * acc.x + acc.y * acc.y + acc.z * acc.z + acc.w * acc.w;
#pragma unroll
    for (int o = 16; o; o >>= 1) ss += __shfl_xor_sync(FM, ss, o);
    float sc = rsqrtf(fmaxf(ss, 1e-12f));
    if (jb.first) {
        float4 a4;
        a4.x = acc.x * sc; a4.y = acc.y * sc; a4.z = acc.z * sc; a4.w = acc.w * sc;
        *(float4*)(jb.acc + base) = a4;
    } else {
        float4 a4 = *(const float4*)(jb.acc + base);
        a4.x += acc.x * sc; a4.y += acc.y * sc; a4.z += acc.z * sc; a4.w += acc.w * sc;
        *(float4*)(jb.acc + base) = a4;
    }
}

// ------------------- mix (fp32 inputs) -------------------
__global__ void __launch_bounds__(256) mix_kernel(
        const float* __restrict__ C0, const float* __restrict__ C1, const float* __restrict__ C2,
        const float* __restrict__ A0, const float* __restrict__ A1, const float* __restrict__ A2,
        const float* __restrict__ S, const float* __restrict__ S2,
        float* __restrict__ out32, __half* __restrict__ out16, int nrows) {
    int w = (int)((blockIdx.x * (unsigned)blockDim.x + threadIdx.x) >> 5);
    int lane = threadIdx.x & 31;
    if (w >= nrows) return;
    size_t base = (size_t)w * DIMV + lane * 4;
    float4 v = *(const float4*)(g_attvec + lane * 4);
    float4 c0 = *(const float4*)(C0 + base);
    float4 c1 = *(const float4*)(C1 + base);
    float4 c2 = *(const float4*)(C2 + base);
    if (A0) {
        float4 a0 = *(const float4*)(A0 + base);
        float4 a1 = *(const float4*)(A1 + base);
        float4 a2 = *(const float4*)(A2 + base);
        c0.x += a0.x; c0.y += a0.y; c0.z += a0.z; c0.w += a0.w;
        c1.x += a1.x; c1.y += a1.y; c1.z += a1.z; c1.w += a1.w;
        c2.x += a2.x; c2.y += a2.y; c2.z += a2.z; c2.w += a2.w;
    }
    float w0 = c0.x * v.x + c0.y * v.y + c0.z * v.z + c0.w * v.w;
    float w1 = c1.x * v.x + c1.y * v.y + c1.z * v.z + c1.w * v.w;
    float w2 = c2.x * v.x + c2.y * v.y + c2.z * v.z + c2.w * v.w;
#pragma unroll
    for (int o = 16; o; o >>= 1) {
        w0 += __shfl_xor_sync(0xffffffffu, w0, o);
        w1 += __shfl_xor_sync(0xffffffffu, w1, o);
        w2 += __shfl_xor_sync(0xffffffffu, w2, o);
    }
    float m = fmaxf(w0, fmaxf(w1, w2));
    float e0 = expf(w0 - m), e1 = expf(w1 - m), e2 = expf(w2 - m);
    float inv = 1.f / (e0 + e1 + e2);
    e0 *= inv; e1 *= inv; e2 *= inv;
    float4 s = *(const float4*)(S + base);
    if (S2) {
        float4 s2 = *(const float4*)(S2 + base);
        s.x += s2.x; s.y += s2.y; s.z += s2.z; s.w += s2.w;
    }
    float4 o;
    o.x = e0 * c0.x + e1 * c1.x + e2 * c2.x + 0.5f * s.x;
    o.y = e0 * c0.y + e1 * c1.y + e2 * c2.y + 0.5f * s.y;
    o.z = e0 * c0.z + e1 * c1.z + e2 * c2.z + 0.5f * s.z;
    o.w = e0 * c0.w + e1 * c1.w + e2 * c2.w + 0.5f * s.w;
    if (out32) *(float4*)(out32 + base) = o;
    if (out16) {
        union { __half2 h[2]; uint2 u; } cv;
        cv.h[0] = __floats2half2_rn(o.x, o.y);
        cv.h[1] = __floats2half2_rn(o.z, o.w);
        *(uint2*)(out16 + base) = cv.u;
    }
}

// ------------------- mix (fp16 inputs) -------------------
__device__ __forceinline__ float4 ldh4(const __half* p) {
    uint2 r = *(const uint2*)p;
    float2 f0 = __half22float2(*(__half2*)&r.x);
    float2 f1 = __half22float2(*(__half2*)&r.y);
    return make_float4(f0.x, f0.y, f1.x, f1.y);
}

__global__ void __launch_bounds__(256) mix_h_kernel(
        const __half* __restrict__ C0, const __half* __restrict__ C1, const __half* __restrict__ C2,
        const __half* __restrict__ S, __half* __restrict__ out16, int nrows) {
    int w = (int)((blockIdx.x * (unsigned)blockDim.x + threadIdx.x) >> 5);
    int lane = threadIdx.x & 31;
    if (w >= nrows) return;
    size_t base = (size_t)w * DIMV + lane * 4;
    float4 v = *(const float4*)(g_attvec + lane * 4);
    float4 c0 = ldh4(C0 + base);
    float4 c1 = ldh4(C1 + base);
    float4 c2 = ldh4(C2 + base);
    float w0 = c0.x * v.x + c0.y * v.y + c0.z * v.z + c0.w * v.w;
    float w1 = c1.x * v.x + c1.y * v.y + c1.z * v.z + c1.w * v.w;
    float w2 = c2.x * v.x + c2.y * v.y + c2.z * v.z + c2.w * v.w;
#pragma unroll
    for (int o = 16; o; o >>= 1) {
        w0 += __shfl_xor_sync(0xffffffffu, w0, o);
        w1 += __shfl_xor_sync(0xffffffffu, w1, o);
        w2 += __shfl_xor_sync(0xffffffffu, w2, o);
    }
    float m = fmaxf(w0, fmaxf(w1, w2));
    float e0 = expf(w0 - m), e1 = expf(w1 - m), e2 = expf(w2 - m);
    float inv = 1.f / (e0 + e1 + e2);
    e0 *= inv; e1 *= inv; e2 *= inv;
    float4 s = ldh4(S + base);
    float4 o;
    o.x = e0 * c0.x + e1 * c1.x + e2 * c2.x + 0.5f * s.x;
    o.y = e0 * c0.y + e1 * c1.y + e2 * c2.y + 0.5f * s.y;
    o.z = e0 * c0.z + e1 * c1.z + e2 * c2.z + 0.5f * s.z;
    o.w = e0 * c0.w + e1 * c1.w + e2 * c2.w + 0.5f * s.w;
    union { __half2 h[2]; uint2 u; } cv;
    cv.h[0] = __floats2half2_rn(o.x, o.y);
    cv.h[1] = __floats2half2_rn(o.z, o.w);
    *(uint2*)(out16 + base) = cv.u;
}

// ------------------- item output -------------------
__global__ void __launch_bounds__(256) item_out_kernel(const float* __restrict__ ie,
                                                       const float* __restrict__ ia,
                                                       float* __restrict__ out) {
    int i = blockIdx.x * blockDim.x + threadIdx.x;
    if (i < (int)(IFl / 4)) {
        float4 a = __ldg((const float4*)ie + i);
        float4 b = *((const float4*)ia + i);
        a.x += b.x; a.y += b.y; a.z += b.z; a.w += b.w;
        *((float4*)out + i) = a;
    }
}

// ------------------- host orchestration -------------------
extern "C" void kernel_launch(void* const* d_in, const int* in_sizes, int n_in,
                              void* d_out, int out_size) {
    const float* u_emb = (const float*)d_in[0];
    const float* i_emb = (const float*)d_in[1];
    const float* gW = (const float*)d_in[2];
    const float* gB = (const float*)d_in[3];
    const float* att = (const float*)d_in[4];
    const float* attm = (const float*)d_in[5];
    const int* Hr[3] = {(const int*)d_in[6], (const int*)d_in[9], (const int*)d_in[12]};
    const int* Hc[3] = {(const int*)d_in[7], (const int*)d_in[10], (const int*)d_in[13]};
    const float* Hv[3] = {(const float*)d_in[8], (const float*)d_in[11], (const float*)d_in[14]};
    const int* Rr = (const int*)d_in[15];
    const int* Rc = (const int*)d_in[16];
    const float* Rv = (const float*)d_in[17];
    int EH = in_sizes[6], ER = in_sizes[15];
    float* out = (float*)d_out;

    static float* B = nullptr;
    static __half* H = nullptr;
    static int *cnt = nullptr, *cur = nullptr, *offs = nullptr, *aux = nullptr;
    static int2* pair = nullptr;
    static cudaStream_t s2 = nullptr;
    static cudaEvent_t evFork = nullptr, evJoin = nullptr;
    static size_t smem = (size_t)(DIMV * 132 + GROWS * DIMV) * sizeof(float);
    if (!B) {
        cudaGetSymbolAddress((void**)&B, g_buf);
        cudaGetSymbolAddress((void**)&H, g_hbuf);
        cudaGetSymbolAddress((void**)&cnt, g_cnt);
        cudaGetSymbolAddress((void**)&cur, g_cur);
        cudaGetSymbolAddress((void**)&offs, g_offs);
        cudaGetSymbolAddress((void**)&pair, g_pair);
        cudaGetSymbolAddress((void**)&aux, g_aux);
        cudaFuncSetAttribute(gate_kernel, cudaFuncAttributeMaxDynamicSharedMemorySize, (int)smem);
        cudaStreamCreateWithFlags(&s2, cudaStreamNonBlocking);
        cudaEventCreateWithFlags(&evFork, cudaEventDisableTiming);
        cudaEventCreateWithFlags(&evJoin, cudaEventDisableTiming);
    }
    float* accc = B + O_ACCC;
    float* sacc = B + O_SACC;
    float* iacc = B + O_IACC;
    float* gate = B + O_GATE;
    __half* gate16 = H + H_GATE;
    __half* curA16 = H + H_CURA;
    __half* mix16 = H + H_MIX;
    __half* s1_16 = H + H_S1;
    __half* i1_16 = H + H_I1;
    __half* iemb16 = H + H_IEMB;

#define GP(c) (gate + (size_t)(c) * UF)
#define GP16(c) (gate16 + (size_t)(c) * UF)
#define CA16(c) (curA16 + (size_t)(c) * UF)
#define AC(c) (accc + (size_t)(c) * UF)

    Build5 bj;
    for (int k = 0; k < 3; k++)
        bj.j[k] = {Hr[k], Hc[k], Hv[k], cnt + k * NU, cur + k * NU, offs + k * OSTR,
                   pair + (size_t)k * EHMAX, EH, NU};
    bj.j[3] = {Rr, Rc, Rv, cnt + 3 * NU, cur + 3 * NU, offs + 3 * OSTR,
               pair + 3 * (size_t)EHMAX, ER, NU};
    bj.j[4] = {Rc, Rr, Rv, cnt + 4 * NU, cur + 4 * NU, offs + 4 * OSTR,
               pair + 3 * (size_t)EHMAX + ERMAX, ER, NI};
    // balanced 1D grid for edge-parallel build kernels
    {
        int be[5];
        for (int k = 0; k < 5; k++) be[k] = (bj.j[k].ne + 255) / 256;
        bj.bstart[0] = 0;
        for (int k = 0; k < 5; k++) bj.bstart[k + 1] = bj.bstart[k] + be[k];
    }

    const int* offsR = bj.j[3].offs;  const int2* pairR = bj.j[3].pair;
    const int* offsRT = bj.j[4].offs; const int2* pairRT = bj.j[4].pair;

    // ---- fork: CSR build on s2, dense prologue on main ----
    cudaEventRecord(evFork, 0);
    cudaStreamWaitEvent(s2, evFork, 0);

    cudaMemsetAsync(cnt, 0, CNT_TOT * sizeof(int), s2);
    count_kernel<<<bj.bstart[5], 256, 0, s2>>>(bj);
    scan_chunks_kernel<<<dim3(NCHU, 5), 256, 0, s2>>>(bj, aux);
    scan_aux_kernel<<<1, 160, 0, s2>>>(bj, aux);
    scan_apply_kernel<<<dim3(NCHU, 5), 256, 0, s2>>>(bj, aux);
    scatter_kernel<<<bj.bstart[5], 256, 0, s2>>>(bj);
    cudaEventRecord(evJoin, s2);

    attvec_kernel<<<1, 128>>>(att, attm);
    f2h_kernel<<<(int)((IFl / 4 + 255) / 256), 256>>>(i_emb, iemb16, (int)(IFl / 4));
    gate_kernel<<<dim3(448, 4), 128, smem>>>(u_emb, gW, gB, gate, gate16);

    int mixb = (NU + 7) / 8;
    const int BU = (NU + 7) / 8;
    const int BI = (NI + 7) / 8;

    mix_kernel<<<mixb, 256>>>(GP(0), GP(1), GP(2), nullptr, nullptr, nullptr,
                              GP(3), nullptr, nullptr, mix16, NU);

    cudaStreamWaitEvent(0, evJoin, 0);   // join before SpMM

    // ---------------- layer 1: 5 balanced jobs (all acc first-write) ----------------
    {
        Csr5 a;
        for (int k = 0; k < 3; k++)
            a.j[k] = {bj.j[k].offs, bj.j[k].pair, GP16(k), CA16(k), AC(k), NU, 1};
        a.j[3] = {offsRT, pairRT, mix16, i1_16, iacc, NI, 1};    // item1 = R^T @ mixed
        a.j[4] = {offsR, pairR, iemb16, s1_16, sacc, NU, 1};     // s1 = R @ i_emb
        a.bstart[0] = 0; a.bstart[1] = BU; a.bstart[2] = 2 * BU; a.bstart[3] = 3 * BU;
        a.bstart[4] = 3 * BU + BI; a.bstart[5] = 4 * BU + BI;
        spmm_csr5_kernel<<<a.bstart[5], 256>>>(a);
    }

    // ---------------- layer 2 ----------------
    mix_h_kernel<<<mixb, 256>>>(CA16(0), CA16(1), CA16(2), s1_16, mix16, NU);
    {
        Csr5 a;
        for (int k = 0; k < 3; k++)
            a.j[k] = {bj.j[k].offs, bj.j[k].pair, CA16(k), nullptr, AC(k), NU, 0};
        a.j[3] = {offsRT, pairRT, mix16, nullptr, iacc, NI, 0};  // l2n(R^T @ mixed2)
        a.j[4] = {offsR, pairR, i1_16, nullptr, sacc, NU, 0};    // l2n(R @ item1)
        a.bstart[0] = 0; a.bstart[1] = BU; a.bstart[2] = 2 * BU; a.bstart[3] = 3 * BU;
        a.bstart[4] = 3 * BU + BI; a.bstart[5] = 4 * BU + BI;
        spmm_csr5_kernel<<<a.bstart[5], 256>>>(a);
    }

    // ---------------- final ----------------
    mix_kernel<<<mixb, 256>>>(GP(0), GP(1), GP(2), AC(0), AC(1), AC(2),
                              GP(3), sacc, out, nullptr, NU);
    item_out_kernel<<<(int)((IFl / 4 + 255) / 256), 256>>>(i_emb, iacc, out + (size_t)NU * DIMV);
}

// round 12
// speedup vs baseline: 1.5019x; 1.0356x over previous
#include <cuda_runtime.h>
#include <cuda_fp16.h>
#include <cstdint>

#define NU 50000
#define NI 25000
#define DIMV 128
#define GROWS 16
#define EHMAX 600000
#define ERMAX 1000000
#define CHUNK 1024
#define NCHU 49
#define OSTR 50016

#define UF ((size_t)NU * DIMV)
#define IFl ((size_t)NI * DIMV)

// ------------------- fp32 scratch: layer-1 norms only -------------------
// accc[3UF] | sacc[UF] | iacc[IF]   (all write-first, no memset needed)
#define O_ACCC ((size_t)0)
#define O_SACC (3 * UF)
#define O_IACC (4 * UF)
#define TOTALF (4 * UF + IFl)
__device__ __align__(16) float g_buf[TOTALF];

// ------------------- fp16 scratch -------------------
#define H_GATE ((size_t)0)          // 4 channels
#define H_CURA (4 * UF)             // 3 channels, layer-1 H outputs (raw)
#define H_MIX  (7 * UF)
#define H_S1   (8 * UF)
#define H_N2   (9 * UF)             // 3 channels, l2n(layer-2 H outputs)
#define H_S2N  (12 * UF)            // l2n(layer-2 R output)
#define H_I1   (13 * UF)
#define H_I2N  (13 * UF + IFl)      // l2n(layer-2 RT output)
#define H_IEMB (13 * UF + 2 * IFl)
#define TOTALH (13 * UF + 3 * IFl)
__device__ __align__(16) __half g_hbuf[TOTALH];

__device__ float g_attvec[DIMV];

// ------------------- CSR scratch -------------------
#define CNT_TOT (4 * NU + NI)
#define OFFS_TOT (4 * OSTR + NI + 16)
#define PE_TOT (3 * EHMAX + 2 * ERMAX)
__device__ __align__(16) int g_cnt[CNT_TOT];
__device__ __align__(16) int g_cur[CNT_TOT];
__device__ __align__(16) int g_offs[OFFS_TOT];
__device__ __align__(16) int2 g_pair[PE_TOT];
__device__ int g_aux[5 * 64];

// ------------------- attention vector: v = M @ a -------------------
__global__ void attvec_kernel(const float* __restrict__ att, const float* __restrict__ mat) {
    int j = threadIdx.x;
    float s = 0.f;
#pragma unroll 8
    for (int d = 0; d < DIMV; d++) s += mat[j * DIMV + d] * att[d];
    g_attvec[j] = s;
}

// ------------------- f32 -> f16 conversion -------------------
__global__ void __launch_bounds__(256) f2h_kernel(const float* __restrict__ src,
                                                  __half* __restrict__ dst, int n4) {
    int i = blockIdx.x * 256 + threadIdx.x;
    if (i < n4) {
        float4 v = __ldg((const float4*)src + i);
        union { __half2 h[2]; uint2 u; } cv;
        cv.h[0] = __floats2half2_rn(v.x, v.y);
        cv.h[1] = __floats2half2_rn(v.z, v.w);
        *(uint2*)(dst + (size_t)i * 4) = cv.u;
    }
}

// ------------------- gating with packed f32x2 FFMA, fp16-only output -------------------
__device__ __forceinline__ void ffma2(unsigned long long& c, unsigned long long a, unsigned long long b) {
    asm("fma.rn.f32x2 %0, %1, %2, %3;" : "=l"(c) : "l"(a), "l"(b), "l"(c));
}

__global__ void __launch_bounds__(128) gate_kernel(const float* __restrict__ U,
                                                   const float* __restrict__ W4,
                                                   const float* __restrict__ B4,
                                                   __half* __restrict__ gate16) {
    extern __shared__ float sm[];
    float* Wt = sm;
    float* Us = sm + DIMV * 132;
    int t = threadIdx.x;
    int c = blockIdx.y;
    const float* W = W4 + c * DIMV * DIMV;
    float b = B4[c * DIMV + t];
    __half* out16 = gate16 + (size_t)c * UF;
    unsigned long long bp = (unsigned long long)__float_as_uint(b);

    for (int k = 0; k < DIMV; k++) Wt[t * 132 + k] = W[k * DIMV + t];

    for (int r0 = blockIdx.x * GROWS; r0 < NU; r0 += gridDim.x * GROWS) {
        __syncthreads();
#pragma unroll
        for (int r = 0; r < GROWS; r++) Us[r * DIMV + t] = U[(size_t)(r0 + r) * DIMV + t];
        __syncthreads();
        unsigned long long acc2[GROWS];
#pragma unroll
        for (int r = 0; r < GROWS; r++) acc2[r] = bp;
#pragma unroll 4
        for (int k = 0; k < DIMV; k += 4) {
            ulonglong2 w2 = *(const ulonglong2*)&Wt[t * 132 + k];
#pragma unroll
            for (int r = 0; r < GROWS; r++) {
                ulonglong2 u2 = *(const ulonglong2*)&Us[r * DIMV + k];
                ffma2(acc2[r], u2.x, w2.x);
                ffma2(acc2[r], u2.y, w2.y);
            }
        }
#pragma unroll
        for (int r = 0; r < GROWS; r++) {
            float lo = __uint_as_float((unsigned)acc2[r]);
            float hi = __uint_as_float((unsigned)(acc2[r] >> 32));
            float a = lo + hi;
            float uv = Us[r * DIMV + t];
            float g = uv / (1.f + expf(-a));
            out16[(size_t)(r0 + r) * DIMV + t] = __float2half_rn(g);
        }
    }
}

// ------------------- CSR build -------------------
struct BuildJob { const int* rows; const int* cols; const float* vals;
                  int* cnt; int* cur; int* offs; int2* pair; int ne; int nrows; };
struct Build5 { BuildJob j[5]; int bstart[6]; };

__device__ __forceinline__ int build_job_of(const Build5& a, int blk) {
    int k = 0;
#pragma unroll
    for (int q = 1; q < 5; q++) if (blk >= a.bstart[q]) k = q;
    return k;
}

__global__ void __launch_bounds__(256) count_kernel(Build5 a) {
    int k = build_job_of(a, blockIdx.x);
    BuildJob jb = a.j[k];
    int e = (blockIdx.x - a.bstart[k]) * 256 + threadIdx.x;
    if (e < jb.ne) atomicAdd(jb.cnt + __ldg(jb.rows + e), 1);
}

__global__ void __launch_bounds__(256) scan_chunks_kernel(Build5 a, int* __restrict__ aux) {
    BuildJob jb = a.j[blockIdx.y];
    int n = jb.nrows;
    int base = blockIdx.x * CHUNK;
    if (base >= n) return;
    int tid = threadIdx.x;
    int lane = tid & 31, wid = tid >> 5;
    int i = base + tid * 4;
    int4 v = make_int4(0, 0, 0, 0);
    if (i < n) v = *(const int4*)(jb.cnt + i);
    int s = v.x + v.y + v.z + v.w;
    int ss = s;
#pragma unroll
    for (int o = 1; o < 32; o <<= 1) { int tt = __shfl_up_sync(0xffffffffu, ss, o); if (lane >= o) ss += tt; }
    __shared__ int wsum[8];
    if (lane == 31) wsum[wid] = ss;
    __syncthreads();
    if (tid < 8) {
        int w = wsum[tid];
#pragma unroll
        for (int o = 1; o < 8; o <<= 1) { int tt = __shfl_up_sync(0xffu, w, o); if (tid >= o) w += tt; }
        wsum[tid] = w;
    }
    __syncthreads();
    int excl = ss - s + (wid ? wsum[wid - 1] : 0);
    if (i < n) {
        int4 e;
        e.x = excl; e.y = excl + v.x; e.z = e.y + v.y; e.w = e.z + v.z;
        *(int4*)(jb.offs + i) = e;
    }
    if (tid == 255) aux[blockIdx.y * 64 + blockIdx.x] = wsum[7];
}

__global__ void __launch_bounds__(160) scan_aux_kernel(Build5 a, int* __restrict__ aux) {
    int wid = threadIdx.x >> 5;
    if (wid >= 5) return;
    BuildJob jb = a.j[wid];
    int nch = (jb.nrows + CHUNK - 1) / CHUNK;
    int lane = threadIdx.x & 31;
    int carry = 0;
    for (int b0 = 0; b0 < nch; b0 += 32) {
        int idx = b0 + lane;
        int v = (idx < nch) ? aux[wid * 64 + idx] : 0;
        int s = v;
#pragma unroll
        for (int o = 1; o < 32; o <<= 1) { int tt = __shfl_up_sync(0xffffffffu, s, o); if (lane >= o) s += tt; }
        if (idx < nch) aux[wid * 64 + idx] = carry + s - v;
        carry += __shfl_sync(0xffffffffu, s, 31);
    }
    if (lane == 0) jb.offs[jb.nrows] = carry;
}

__global__ void __launch_bounds__(256) scan_apply_kernel(Build5 a, const int* __restrict__ aux) {
    BuildJob jb = a.j[blockIdx.y];
    int n = jb.nrows;
    int base = blockIdx.x * CHUNK;
    if (base >= n) return;
    int add = aux[blockIdx.y * 64 + blockIdx.x];
    int i = base + threadIdx.x * 4;
    if (i < n) {
        int4 e = *(const int4*)(jb.offs + i);
        e.x += add; e.y += add; e.z += add; e.w += add;
        *(int4*)(jb.offs + i) = e;
        *(int4*)(jb.cur + i) = e;
    }
}

__global__ void __launch_bounds__(256) scatter_kernel(Build5 a) {
    int k = build_job_of(a, blockIdx.x);
    BuildJob jb = a.j[k];
    int e = (blockIdx.x - a.bstart[k]) * 256 + threadIdx.x;
    if (e >= jb.ne) return;
    int r = __ldg(jb.rows + e);
    int p = atomicAdd(jb.cur + r, 1);
    jb.pair[p] = make_int2(__ldg(jb.cols + e), __float_as_int(__ldg(jb.vals + e)));
}

// ------------------- CSR SpMM (fp16 gathers) -------------------
// Epilogue modes: Y16 (raw fp16), acc (fp32 l2norm write), Yn16 (fp16 l2norm write)
struct CsrJob { const int* offs; const int2* pair; const __half* X;
                __half* Y16; float* acc; __half* Yn16; int nrows; };
struct Csr5 { CsrJob j[5]; int bstart[6]; };

__device__ __forceinline__ void fma_h(float4& acc, float v, uint2 raw) {
    __half2 h0 = *(__half2*)&raw.x;
    __half2 h1 = *(__half2*)&raw.y;
    float2 f0 = __half22float2(h0);
    float2 f1 = __half22float2(h1);
    acc.x += v * f0.x; acc.y += v * f0.y; acc.z += v * f1.x; acc.w += v * f1.y;
}

__global__ void __launch_bounds__(256) spmm_csr5_kernel(Csr5 a) {
    int blk = blockIdx.x;
    int k = 0;
#pragma unroll
    for (int q = 1; q < 5; q++) if (blk >= a.bstart[q]) k = q;
    CsrJob jb = a.j[k];
    int w = (blk - a.bstart[k]) * 8 + (threadIdx.x >> 5);
    int lane = threadIdx.x & 31;
    if (w >= jb.nrows) return;
    const unsigned FM = 0xffffffffu;
    int start = __ldg(jb.offs + w);
    int end = __ldg(jb.offs + w + 1);
    float4 acc = make_float4(0.f, 0.f, 0.f, 0.f);
    const __half* X = jb.X;
    for (int b = start; b < end; b += 32) {
        int i = b + lane;
        int c = 0; float v = 0.f;
        if (i < end) { int2 pr = __ldg(jb.pair + i); c = pr.x; v = __int_as_float(pr.y); }
        int m = end - b; if (m > 32) m = 32;
        int j = 0;
        for (; j + 4 <= m; j += 4) {
            int c0 = __shfl_sync(FM, c, j + 0);
            int c1 = __shfl_sync(FM, c, j + 1);
            int c2 = __shfl_sync(FM, c, j + 2);
            int c3 = __shfl_sync(FM, c, j + 3);
            uint2 x0 = __ldg((const uint2*)(X + (size_t)c0 * DIMV) + lane);
            uint2 x1 = __ldg((const uint2*)(X + (size_t)c1 * DIMV) + lane);
            uint2 x2 = __ldg((const uint2*)(X + (size_t)c2 * DIMV) + lane);
            uint2 x3 = __ldg((const uint2*)(X + (size_t)c3 * DIMV) + lane);
            float v0 = __shfl_sync(FM, v, j + 0);
            float v1 = __shfl_sync(FM, v, j + 1);
            float v2 = __shfl_sync(FM, v, j + 2);
            float v3 = __shfl_sync(FM, v, j + 3);
            fma_h(acc, v0, x0);
            fma_h(acc, v1, x1);
            fma_h(acc, v2, x2);
            fma_h(acc, v3, x3);
        }
        for (; j < m; j++) {
            int cj = __shfl_sync(FM, c, j);
            float vj = __shfl_sync(FM, v, j);
            uint2 x = __ldg((const uint2*)(X + (size_t)cj * DIMV) + lane);
            fma_h(acc, vj, x);
        }
    }
    size_t base = (size_t)w * DIMV + lane * 4;
    if (jb.Y16) {
        union { __half2 h[2]; uint2 u; } cv;
        cv.h[0] = __floats2half2_rn(acc.x, acc.y);
        cv.h[1] = __floats2half2_rn(acc.z, acc.w);
        *(uint2*)(jb.Y16 + base) = cv.u;
    }
    if (jb.acc || jb.Yn16) {
        float ss = acc.x * acc.x + acc.y * acc.y + acc.z * acc.z + acc.w * acc.w;
#pragma unroll
        for (int o = 16; o; o >>= 1) ss += __shfl_xor_sync(FM, ss, o);
        float sc = rsqrtf(fmaxf(ss, 1e-12f));
        if (jb.acc) {
            float4 a4;
            a4.x = acc.x * sc; a4.y = acc.y * sc; a4.z = acc.z * sc; a4.w = acc.w * sc;
            *(float4*)(jb.acc + base) = a4;
        }
        if (jb.Yn16) {
            union { __half2 h[2]; uint2 u; } cv;
            cv.h[0] = __floats2half2_rn(acc.x * sc, acc.y * sc);
            cv.h[1] = __floats2half2_rn(acc.z * sc, acc.w * sc);
            *(uint2*)(jb.Yn16 + base) = cv.u;
        }
    }
}

// ------------------- helpers -------------------
__device__ __forceinline__ float4 ldh4(const __half* p) {
    uint2 r = *(const uint2*)p;
    float2 f0 = __half22float2(*(__half2*)&r.x);
    float2 f1 = __half22float2(*(__half2*)&r.y);
    return make_float4(f0.x, f0.y, f1.x, f1.y);
}

// ------------------- mix (fp16 inputs) -> fp16 out -------------------
__global__ void __launch_bounds__(256) mix_h_kernel(
        const __half* __restrict__ C0, const __half* __restrict__ C1, const __half* __restrict__ C2,
        const __half* __restrict__ S, __half* __restrict__ out16, int nrows) {
    int w = (int)((blockIdx.x * (unsigned)blockDim.x + threadIdx.x) >> 5);
    int lane = threadIdx.x & 31;
    if (w >= nrows) return;
    size_t base = (size_t)w * DIMV + lane * 4;
    float4 v = *(const float4*)(g_attvec + lane * 4);
    float4 c0 = ldh4(C0 + base);
    float4 c1 = ldh4(C1 + base);
    float4 c2 = ldh4(C2 + base);
    float w0 = c0.x * v.x + c0.y * v.y + c0.z * v.z + c0.w * v.w;
    float w1 = c1.x * v.x + c1.y * v.y + c1.z * v.z + c1.w * v.w;
    float w2 = c2.x * v.x + c2.y * v.y + c2.z * v.z + c2.w * v.w;
#pragma unroll
    for (int o = 16; o; o >>= 1) {
        w0 += __shfl_xor_sync(0xffffffffu, w0, o);
        w1 += __shfl_xor_sync(0xffffffffu, w1, o);
        w2 += __shfl_xor_sync(0xffffffffu, w2, o);
    }
    float m = fmaxf(w0, fmaxf(w1, w2));
    float e0 = expf(w0 - m), e1 = expf(w1 - m), e2 = expf(w2 - m);
    float inv = 1.f / (e0 + e1 + e2);
    e0 *= inv; e1 *= inv; e2 *= inv;
    float4 s = ldh4(S + base);
    float4 o;
    o.x = e0 * c0.x + e1 * c1.x + e2 * c2.x + 0.5f * s.x;
    o.y = e0 * c0.y + e1 * c1.y + e2 * c2.y + 0.5f * s.y;
    o.z = e0 * c0.z + e1 * c1.z + e2 * c2.z + 0.5f * s.z;
    o.w = e0 * c0.w + e1 * c1.w + e2 * c2.w + 0.5f * s.w;
    union { __half2 h[2]; uint2 u; } cv;
    cv.h[0] = __floats2half2_rn(o.x, o.y);
    cv.h[1] = __floats2half2_rn(o.z, o.w);
    *(uint2*)(out16 + base) = cv.u;
}

// ------------------- final mix: C_k = gate16_k + accc_k + n2_k; S = gate16_3 + sacc + s2n -------------------
__global__ void __launch_bounds__(256) mix_final_kernel(
        const __half* __restrict__ gate16, const float* __restrict__ accc,
        const __half* __restrict__ n2, const float* __restrict__ sacc,
        const __half* __restrict__ s2n, float* __restrict__ out, int nrows) {
    int w = (int)((blockIdx.x * (unsigned)blockDim.x + threadIdx.x) >> 5);
    int lane = threadIdx.x & 31;
    if (w >= nrows) return;
    size_t base = (size_t)w * DIMV + lane * 4;
    float4 v = *(const float4*)(g_attvec + lane * 4);
    float4 c[3];
#pragma unroll
    for (int k = 0; k < 3; k++) {
        float4 g = ldh4(gate16 + (size_t)k * UF + base);
        float4 a = *(const float4*)(accc + (size_t)k * UF + base);
        float4 n = ldh4(n2 + (size_t)k * UF + base);
        c[k].x = g.x + a.x + n.x;
        c[k].y = g.y + a.y + n.y;
        c[k].z = g.z + a.z + n.z;
        c[k].w = g.w + a.w + n.w;
    }
    float w0 = c[0].x * v.x + c[0].y * v.y + c[0].z * v.z + c[0].w * v.w;
    float w1 = c[1].x * v.x + c[1].y * v.y + c[1].z * v.z + c[1].w * v.w;
    float w2 = c[2].x * v.x + c[2].y * v.y + c[2].z * v.z + c[2].w * v.w;
#pragma unroll
    for (int o = 16; o; o >>= 1) {
        w0 += __shfl_xor_sync(0xffffffffu, w0, o);
        w1 += __shfl_xor_sync(0xffffffffu, w1, o);
        w2 += __shfl_xor_sync(0xffffffffu, w2, o);
    }
    float m = fmaxf(w0, fmaxf(w1, w2));
    float e0 = expf(w0 - m), e1 = expf(w1 - m), e2 = expf(w2 - m);
    float inv = 1.f / (e0 + e1 + e2);
    e0 *= inv; e1 *= inv; e2 *= inv;
    float4 g3 = ldh4(gate16 + 3 * UF + base);
    float4 sa = *(const float4*)(sacc + base);
    float4 sn = ldh4(s2n + base);
    float4 o;
    o.x = e0 * c[0].x + e1 * c[1].x + e2 * c[2].x + 0.5f * (g3.x + sa.x + sn.x);
    o.y = e0 * c[0].y + e1 * c[1].y + e2 * c[2].y + 0.5f * (g3.y + sa.y + sn.y);
    o.z = e0 * c[0].z + e1 * c[1].z + e2 * c[2].z + 0.5f * (g3.z + sa.z + sn.z);
    o.w = e0 * c[0].w + e1 * c[1].w + e2 * c[2].w + 0.5f * (g3.w + sa.w + sn.w);
    *(float4*)(out + base) = o;
}

// ------------------- item output: out = i_emb + iacc + i2n -------------------
__global__ void __launch_bounds__(256) item_out_kernel(const float* __restrict__ ie,
                                                       const float* __restrict__ ia,
                                                       const __half* __restrict__ i2n,
                                                       float* __restrict__ out) {
    int i = blockIdx.x * blockDim.x + threadIdx.x;
    if (i < (int)(IFl / 4)) {
        float4 a = __ldg((const float4*)ie + i);
        float4 b = *((const float4*)ia + i);
        float4 n = ldh4(i2n + (size_t)i * 4);
        a.x += b.x + n.x; a.y += b.y + n.y; a.z += b.z + n.z; a.w += b.w + n.w;
        *((float4*)out + i) = a;
    }
}

// ------------------- host orchestration -------------------
extern "C" void kernel_launch(void* const* d_in, const int* in_sizes, int n_in,
                              void* d_out, int out_size) {
    const float* u_emb = (const float*)d_in[0];
    const float* i_emb = (const float*)d_in[1];
    const float* gW = (const float*)d_in[2];
    const float* gB = (const float*)d_in[3];
    const float* att = (const float*)d_in[4];
    const float* attm = (const float*)d_in[5];
    const int* Hr[3] = {(const int*)d_in[6], (const int*)d_in[9], (const int*)d_in[12]};
    const int* Hc[3] = {(const int*)d_in[7], (const int*)d_in[10], (const int*)d_in[13]};
    const float* Hv[3] = {(const float*)d_in[8], (const float*)d_in[11], (const float*)d_in[14]};
    const int* Rr = (const int*)d_in[15];
    const int* Rc = (const int*)d_in[16];
    const float* Rv = (const float*)d_in[17];
    int EH = in_sizes[6], ER = in_sizes[15];
    float* out = (float*)d_out;

    static float* B = nullptr;
    static __half* H = nullptr;
    static int *cnt = nullptr, *cur = nullptr, *offs = nullptr, *aux = nullptr;
    static int2* pair = nullptr;
    static cudaStream_t s2 = nullptr;
    static cudaEvent_t evFork = nullptr, evJoin = nullptr;
    static size_t smem = (size_t)(DIMV * 132 + GROWS * DIMV) * sizeof(float);
    if (!B) {
        cudaGetSymbolAddress((void**)&B, g_buf);
        cudaGetSymbolAddress((void**)&H, g_hbuf);
        cudaGetSymbolAddress((void**)&cnt, g_cnt);
        cudaGetSymbolAddress((void**)&cur, g_cur);
        cudaGetSymbolAddress((void**)&offs, g_offs);
        cudaGetSymbolAddress((void**)&pair, g_pair);
        cudaGetSymbolAddress((void**)&aux, g_aux);
        cudaFuncSetAttribute(gate_kernel, cudaFuncAttributeMaxDynamicSharedMemorySize, (int)smem);
        cudaStreamCreateWithFlags(&s2, cudaStreamNonBlocking);
        cudaEventCreateWithFlags(&evFork, cudaEventDisableTiming);
        cudaEventCreateWithFlags(&evJoin, cudaEventDisableTiming);
    }
    float* accc = B + O_ACCC;
    float* sacc = B + O_SACC;
    float* iacc = B + O_IACC;
    __half* gate16 = H + H_GATE;
    __half* curA16 = H + H_CURA;
    __half* mix16 = H + H_MIX;
    __half* s1_16 = H + H_S1;
    __half* n2_16 = H + H_N2;
    __half* s2n16 = H + H_S2N;
    __half* i1_16 = H + H_I1;
    __half* i2n16 = H + H_I2N;
    __half* iemb16 = H + H_IEMB;

#define GP16(c) (gate16 + (size_t)(c) * UF)
#define CA16(c) (curA16 + (size_t)(c) * UF)
#define AC(c) (accc + (size_t)(c) * UF)
#define N2(c) (n2_16 + (size_t)(c) * UF)

    Build5 bj;
    for (int k = 0; k < 3; k++)
        bj.j[k] = {Hr[k], Hc[k], Hv[k], cnt + k * NU, cur + k * NU, offs + k * OSTR,
                   pair + (size_t)k * EHMAX, EH, NU};
    bj.j[3] = {Rr, Rc, Rv, cnt + 3 * NU, cur + 3 * NU, offs + 3 * OSTR,
               pair + 3 * (size_t)EHMAX, ER, NU};
    bj.j[4] = {Rc, Rr, Rv, cnt + 4 * NU, cur + 4 * NU, offs + 4 * OSTR,
               pair + 3 * (size_t)EHMAX + ERMAX, ER, NI};
    {
        int be[5];
        for (int k = 0; k < 5; k++) be[k] = (bj.j[k].ne + 255) / 256;
        bj.bstart[0] = 0;
        for (int k = 0; k < 5; k++) bj.bstart[k + 1] = bj.bstart[k] + be[k];
    }

    const int* offsR = bj.j[3].offs;  const int2* pairR = bj.j[3].pair;
    const int* offsRT = bj.j[4].offs; const int2* pairRT = bj.j[4].pair;

    // ---- fork: CSR build on s2, dense prologue on main ----
    cudaEventRecord(evFork, 0);
    cudaStreamWaitEvent(s2, evFork, 0);

    cudaMemsetAsync(cnt, 0, CNT_TOT * sizeof(int), s2);
    count_kernel<<<bj.bstart[5], 256, 0, s2>>>(bj);
    scan_chunks_kernel<<<dim3(NCHU, 5), 256, 0, s2>>>(bj, aux);
    scan_aux_kernel<<<1, 160, 0, s2>>>(bj, aux);
    scan_apply_kernel<<<dim3(NCHU, 5), 256, 0, s2>>>(bj, aux);
    scatter_kernel<<<bj.bstart[5], 256, 0, s2>>>(bj);
    cudaEventRecord(evJoin, s2);

    attvec_kernel<<<1, 128>>>(att, attm);
    f2h_kernel<<<(int)((IFl / 4 + 255) / 256), 256>>>(i_emb, iemb16, (int)(IFl / 4));
    gate_kernel<<<dim3(448, 4), 128, smem>>>(u_emb, gW, gB, gate16);

    int mixb = (NU + 7) / 8;
    const int BU = (NU + 7) / 8;
    const int BI = (NI + 7) / 8;

    // layer-1 mix: fp16 gates, S = gate channel 3
    mix_h_kernel<<<mixb, 256>>>(GP16(0), GP16(1), GP16(2), GP16(3), mix16, NU);

    cudaStreamWaitEvent(0, evJoin, 0);   // join before SpMM

    // ---------------- layer 1: raw fp16 out + fp32 l2norm write ----------------
    {
        Csr5 a;
        for (int k = 0; k < 3; k++)
            a.j[k] = {bj.j[k].offs, bj.j[k].pair, GP16(k), CA16(k), AC(k), nullptr, NU};
        a.j[3] = {offsRT, pairRT, mix16, i1_16, iacc, nullptr, NI};  // item1 = R^T @ mixed
        a.j[4] = {offsR, pairR, iemb16, s1_16, sacc, nullptr, NU};   // s1 = R @ i_emb
        a.bstart[0] = 0; a.bstart[1] = BU; a.bstart[2] = 2 * BU; a.bstart[3] = 3 * BU;
        a.bstart[4] = 3 * BU + BI; a.bstart[5] = 4 * BU + BI;
        spmm_csr5_kernel<<<a.bstart[5], 256>>>(a);
    }

    // ---------------- layer 2: l2norm fp16 write only ----------------
    mix_h_kernel<<<mixb, 256>>>(CA16(0), CA16(1), CA16(2), s1_16, mix16, NU);
    {
        Csr5 a;
        for (int k = 0; k < 3; k++)
            a.j[k] = {bj.j[k].offs, bj.j[k].pair, CA16(k), nullptr, nullptr, N2(k), NU};
        a.j[3] = {offsRT, pairRT, mix16, nullptr, nullptr, i2n16, NI};  // l2n(R^T @ mixed2)
        a.j[4] = {offsR, pairR, i1_16, nullptr, nullptr, s2n16, NU};    // l2n(R @ item1)
        a.bstart[0] = 0; a.bstart[1] = BU; a.bstart[2] = 2 * BU; a.bstart[3] = 3 * BU;
        a.bstart[4] = 3 * BU + BI; a.bstart[5] = 4 * BU + BI;
        spmm_csr5_kernel<<<a.bstart[5], 256>>>(a);
    }

    // ---------------- final ----------------
    mix_final_kernel<<<mixb, 256>>>(gate16, accc, n2_16, sacc, s2n16, out, NU);
    item_out_kernel<<<(int)((IFl / 4 + 255) / 256), 256>>>(i_emb, iacc, i2n16,
                                                           out + (size_t)NU * DIMV);
}

// round 13
// speedup vs baseline: 1.7121x; 1.1400x over previous
#include <cuda_runtime.h>
#include <cuda_fp16.h>
#include <mma.h>
#include <cstdint>

using namespace nvcuda;

#define NU 50000
#define NI 25000
#define DIMV 128
#define EHMAX 600000
#define ERMAX 1000000
#define CHUNK 1024
#define NCHU 49
#define OSTR 50016

#define UF ((size_t)NU * DIMV)
#define IFl ((size_t)NI * DIMV)

// ------------------- fp32 scratch: layer-1 norms only -------------------
#define O_ACCC ((size_t)0)
#define O_SACC (3 * UF)
#define O_IACC (4 * UF)
#define TOTALF (4 * UF + IFl)
__device__ __align__(16) float g_buf[TOTALF];

// ------------------- fp16 scratch -------------------
#define H_GATE ((size_t)0)          // 4 channels
#define H_CURA (4 * UF)             // 3 channels, layer-1 H outputs (raw)
#define H_MIX  (7 * UF)
#define H_S1   (8 * UF)
#define H_N2   (9 * UF)             // 3 channels, l2n(layer-2 H outputs)
#define H_S2N  (12 * UF)            // l2n(layer-2 R output)
#define H_I1   (13 * UF)
#define H_I2N  (13 * UF + IFl)      // l2n(layer-2 RT output)
#define H_IEMB (13 * UF + 2 * IFl)
#define TOTALH (13 * UF + 3 * IFl)
__device__ __align__(16) __half g_hbuf[TOTALH];

__device__ float g_attvec[DIMV];

// ------------------- CSR scratch -------------------
#define CNT_TOT (4 * NU + NI)
#define OFFS_TOT (4 * OSTR + NI + 16)
#define PE_TOT (3 * EHMAX + 2 * ERMAX)
__device__ __align__(16) int g_cnt[CNT_TOT];
__device__ __align__(16) int g_cur[CNT_TOT];
__device__ __align__(16) int g_offs[OFFS_TOT];
__device__ __align__(16) int2 g_pair[PE_TOT];
__device__ int g_aux[5 * 64];

// ------------------- attention vector: v = M @ a -------------------
__global__ void attvec_kernel(const float* __restrict__ att, const float* __restrict__ mat) {
    int j = threadIdx.x;
    float s = 0.f;
#pragma unroll 8
    for (int d = 0; d < DIMV; d++) s += mat[j * DIMV + d] * att[d];
    g_attvec[j] = s;
}

// ------------------- f32 -> f16 conversion -------------------
__global__ void __launch_bounds__(256) f2h_kernel(const float* __restrict__ src,
                                                  __half* __restrict__ dst, int n4) {
    int i = blockIdx.x * 256 + threadIdx.x;
    if (i < n4) {
        float4 v = __ldg((const float4*)src + i);
        union { __half2 h[2]; uint2 u; } cv;
        cv.h[0] = __floats2half2_rn(v.x, v.y);
        cv.h[1] = __floats2half2_rn(v.z, v.w);
        *(uint2*)(dst + (size_t)i * 4) = cv.u;
    }
}

// ------------------- gating via tensor-core HMMA (wmma fp16, fp32 accum) -------------------
// G_c = U * sigmoid(U @ W_c + b_c), fp16 output.
// Block: 256 threads (8 warps), 1 row-tile = 128 rows. Shared: W(fp16) + U(fp16) + stage(fp32).
#define GLDM 136          // half stride (mult of 8)
#define SLDM 136          // float stride (mult of 4)
#define SM_W 0                                  // half[128*136]
#define SM_U (128 * GLDM)                       // half[128*136]
#define SM_S_BYTES (2 * 128 * GLDM * 2)         // byte offset of stage
#define GATE_SMEM (SM_S_BYTES + 128 * SLDM * 4)

__global__ void __launch_bounds__(256) gate_mma_kernel(const float* __restrict__ U,
                                                       const float* __restrict__ W4,
                                                       const float* __restrict__ B4,
                                                       __half* __restrict__ gate16) {
    extern __shared__ __half smh[];
    __half* Wsh = smh + SM_W;
    __half* Ush = smh + SM_U;
    float* St = (float*)((char*)smh + SM_S_BYTES);
    int tid = threadIdx.x;
    int warp = tid >> 5;
    int c = blockIdx.y;
    const float* W = W4 + c * DIMV * DIMV;
    __half* out16 = gate16 + (size_t)c * UF;

    // load W (128x128) into shared fp16, row-major (k rows, n cols)
    for (int i = tid; i < DIMV * DIMV; i += 256) {
        int k = i >> 7, n = i & 127;
        Wsh[k * GLDM + n] = __float2half_rn(W[i]);
    }
    // per-thread fixed column for the epilogue
    int ncol = tid & 127;
    float bias = B4[c * DIMV + ncol];

    for (int tile = blockIdx.x * 128; tile < NU; tile += gridDim.x * 128) {
        __syncthreads();   // Ut/St safe to overwrite (epilogue of prev iter done)
        // load U tile (128 rows) into shared fp16; zero-pad rows beyond NU
        for (int i = tid; i < 128 * DIMV; i += 256) {
            int r = i >> 7, n = i & 127;
            int gr = tile + r;
            float v = (gr < NU) ? U[(size_t)gr * DIMV + n] : 0.f;
            Ush[r * GLDM + n] = __float2half_rn(v);
        }
        __syncthreads();

        // each warp: 16 rows x 128 cols
        {
            wmma::fragment<wmma::accumulator, 16, 16, 16, float> fc[8];
#pragma unroll
            for (int n0 = 0; n0 < 8; n0++) wmma::fill_fragment(fc[n0], 0.f);
#pragma unroll
            for (int k0 = 0; k0 < 8; k0++) {
                wmma::fragment<wmma::matrix_a, 16, 16, 16, __half, wmma::row_major> fa;
                wmma::load_matrix_sync(fa, Ush + (warp * 16) * GLDM + k0 * 16, GLDM);
#pragma unroll
                for (int n0 = 0; n0 < 8; n0++) {
                    wmma::fragment<wmma::matrix_b, 16, 16, 16, __half, wmma::row_major> fb;
                    wmma::load_matrix_sync(fb, Wsh + (k0 * 16) * GLDM + n0 * 16, GLDM);
                    wmma::mma_sync(fc[n0], fa, fb, fc[n0]);
                }
            }
#pragma unroll
            for (int n0 = 0; n0 < 8; n0++)
                wmma::store_matrix_sync(St + (warp * 16) * SLDM + n0 * 16, fc[n0],
                                        SLDM, wmma::mem_row_major);
        }
        __syncthreads();

        // epilogue: g = u * sigmoid(acc + b), fp16 out
        for (int i = tid; i < 128 * DIMV; i += 256) {
            int r = i >> 7;              // n == ncol (i & 127 == tid & 127)
            int gr = tile + r;
            if (gr < NU) {
                float a = St[r * SLDM + ncol] + bias;
                float u = __half2float(Ush[r * GLDM + ncol]);
                out16[(size_t)gr * DIMV + ncol] = __float2half_rn(u / (1.f + expf(-a)));
            }
        }
    }
}

// ------------------- CSR build -------------------
struct BuildJob { const int* rows; const int* cols; const float* vals;
                  int* cnt; int* cur; int* offs; int2* pair; int ne; int nrows; };
struct Build5 { BuildJob j[5]; int bstart[6]; };

__device__ __forceinline__ int build_job_of(const Build5& a, int blk) {
    int k = 0;
#pragma unroll
    for (int q = 1; q < 5; q++) if (blk >= a.bstart[q]) k = q;
    return k;
}

__global__ void __launch_bounds__(256) count_kernel(Build5 a) {
    int k = build_job_of(a, blockIdx.x);
    BuildJob jb = a.j[k];
    int e = (blockIdx.x - a.bstart[k]) * 256 + threadIdx.x;
    if (e < jb.ne) atomicAdd(jb.cnt + __ldg(jb.rows + e), 1);
}

__global__ void __launch_bounds__(256) scan_chunks_kernel(Build5 a, int* __restrict__ aux) {
    BuildJob jb = a.j[blockIdx.y];
    int n = jb.nrows;
    int base = blockIdx.x * CHUNK;
    if (base >= n) return;
    int tid = threadIdx.x;
    int lane = tid & 31, wid = tid >> 5;
    int i = base + tid * 4;
    int4 v = make_int4(0, 0, 0, 0);
    if (i < n) v = *(const int4*)(jb.cnt + i);
    int s = v.x + v.y + v.z + v.w;
    int ss = s;
#pragma unroll
    for (int o = 1; o < 32; o <<= 1) { int tt = __shfl_up_sync(0xffffffffu, ss, o); if (lane >= o) ss += tt; }
    __shared__ int wsum[8];
    if (lane == 31) wsum[wid] = ss;
    __syncthreads();
    if (tid < 8) {
        int w = wsum[tid];
#pragma unroll
        for (int o = 1; o < 8; o <<= 1) { int tt = __shfl_up_sync(0xffu, w, o); if (tid >= o) w += tt; }
        wsum[tid] = w;
    }
    __syncthreads();
    int excl = ss - s + (wid ? wsum[wid - 1] : 0);
    if (i < n) {
        int4 e;
        e.x = excl; e.y = excl + v.x; e.z = e.y + v.y; e.w = e.z + v.z;
        *(int4*)(jb.offs + i) = e;
    }
    if (tid == 255) aux[blockIdx.y * 64 + blockIdx.x] = wsum[7];
}

__global__ void __launch_bounds__(160) scan_aux_kernel(Build5 a, int* __restrict__ aux) {
    int wid = threadIdx.x >> 5;
    if (wid >= 5) return;
    BuildJob jb = a.j[wid];
    int nch = (jb.nrows + CHUNK - 1) / CHUNK;
    int lane = threadIdx.x & 31;
    int carry = 0;
    for (int b0 = 0; b0 < nch; b0 += 32) {
        int idx = b0 + lane;
        int v = (idx < nch) ? aux[wid * 64 + idx] : 0;
        int s = v;
#pragma unroll
        for (int o = 1; o < 32; o <<= 1) { int tt = __shfl_up_sync(0xffffffffu, s, o); if (lane >= o) s += tt; }
        if (idx < nch) aux[wid * 64 + idx] = carry + s - v;
        carry += __shfl_sync(0xffffffffu, s, 31);
    }
    if (lane == 0) jb.offs[jb.nrows] = carry;
}

__global__ void __launch_bounds__(256) scan_apply_kernel(Build5 a, const int* __restrict__ aux) {
    BuildJob jb = a.j[blockIdx.y];
    int n = jb.nrows;
    int base = blockIdx.x * CHUNK;
    if (base >= n) return;
    int add = aux[blockIdx.y * 64 + blockIdx.x];
    int i = base + threadIdx.x * 4;
    if (i < n) {
        int4 e = *(const int4*)(jb.offs + i);
        e.x += add; e.y += add; e.z += add; e.w += add;
        *(int4*)(jb.offs + i) = e;
        *(int4*)(jb.cur + i) = e;
    }
}

__global__ void __launch_bounds__(256) scatter_kernel(Build5 a) {
    int k = build_job_of(a, blockIdx.x);
    BuildJob jb = a.j[k];
    int e = (blockIdx.x - a.bstart[k]) * 256 + threadIdx.x;
    if (e >= jb.ne) return;
    int r = __ldg(jb.rows + e);
    int p = atomicAdd(jb.cur + r, 1);
    jb.pair[p] = make_int2(__ldg(jb.cols + e), __float_as_int(__ldg(jb.vals + e)));
}

// ------------------- CSR SpMM (fp16 gathers) -------------------
struct CsrJob { const int* offs; const int2* pair; const __half* X;
                __half* Y16; float* acc; __half* Yn16; int nrows; };
struct Csr5 { CsrJob j[5]; int bstart[6]; };

__device__ __forceinline__ void fma_h(float4& acc, float v, uint2 raw) {
    __half2 h0 = *(__half2*)&raw.x;
    __half2 h1 = *(__half2*)&raw.y;
    float2 f0 = __half22float2(h0);
    float2 f1 = __half22float2(h1);
    acc.x += v * f0.x; acc.y += v * f0.y; acc.z += v * f1.x; acc.w += v * f1.y;
}

__global__ void __launch_bounds__(256) spmm_csr5_kernel(Csr5 a) {
    int blk = blockIdx.x;
    int k = 0;
#pragma unroll
    for (int q = 1; q < 5; q++) if (blk >= a.bstart[q]) k = q;
    CsrJob jb = a.j[k];
    int w = (blk - a.bstart[k]) * 8 + (threadIdx.x >> 5);
    int lane = threadIdx.x & 31;
    if (w >= jb.nrows) return;
    const unsigned FM = 0xffffffffu;
    int start = __ldg(jb.offs + w);
    int end = __ldg(jb.offs + w + 1);
    float4 acc = make_float4(0.f, 0.f, 0.f, 0.f);
    const __half* X = jb.X;
    for (int b = start; b < end; b += 32) {
        int i = b + lane;
        int c = 0; float v = 0.f;
        if (i < end) { int2 pr = __ldg(jb.pair + i); c = pr.x; v = __int_as_float(pr.y); }
        int m = end - b; if (m > 32) m = 32;
        int j = 0;
        for (; j + 4 <= m; j += 4) {
            int c0 = __shfl_sync(FM, c, j + 0);
            int c1 = __shfl_sync(FM, c, j + 1);
            int c2 = __shfl_sync(FM, c, j + 2);
            int c3 = __shfl_sync(FM, c, j + 3);
            uint2 x0 = __ldg((const uint2*)(X + (size_t)c0 * DIMV) + lane);
            uint2 x1 = __ldg((const uint2*)(X + (size_t)c1 * DIMV) + lane);
            uint2 x2 = __ldg((const uint2*)(X + (size_t)c2 * DIMV) + lane);
            uint2 x3 = __ldg((const uint2*)(X + (size_t)c3 * DIMV) + lane);
            float v0 = __shfl_sync(FM, v, j + 0);
            float v1 = __shfl_sync(FM, v, j + 1);
            float v2 = __shfl_sync(FM, v, j + 2);
            float v3 = __shfl_sync(FM, v, j + 3);
            fma_h(acc, v0, x0);
            fma_h(acc, v1, x1);
            fma_h(acc, v2, x2);
            fma_h(acc, v3, x3);
        }
        for (; j < m; j++) {
            int cj = __shfl_sync(FM, c, j);
            float vj = __shfl_sync(FM, v, j);
            uint2 x = __ldg((const uint2*)(X + (size_t)cj * DIMV) + lane);
            fma_h(acc, vj, x);
        }
    }
    size_t base = (size_t)w * DIMV + lane * 4;
    if (jb.Y16) {
        union { __half2 h[2]; uint2 u; } cv;
        cv.h[0] = __floats2half2_rn(acc.x, acc.y);
        cv.h[1] = __floats2half2_rn(acc.z, acc.w);
        *(uint2*)(jb.Y16 + base) = cv.u;
    }
    if (jb.acc || jb.Yn16) {
        float ss = acc.x * acc.x + acc.y * acc.y + acc.z * acc.z + acc.w * acc.w;
#pragma unroll
        for (int o = 16; o; o >>= 1) ss += __shfl_xor_sync(FM, ss, o);
        float sc = rsqrtf(fmaxf(ss, 1e-12f));
        if (jb.acc) {
            float4 a4;
            a4.x = acc.x * sc; a4.y = acc.y * sc; a4.z = acc.z * sc; a4.w = acc.w * sc;
            *(float4*)(jb.acc + base) = a4;
        }
        if (jb.Yn16) {
            union { __half2 h[2]; uint2 u; } cv;
            cv.h[0] = __floats2half2_rn(acc.x * sc, acc.y * sc);
            cv.h[1] = __floats2half2_rn(acc.z * sc, acc.w * sc);
            *(uint2*)(jb.Yn16 + base) = cv.u;
        }
    }
}

// ------------------- helpers -------------------
__device__ __forceinline__ float4 ldh4(const __half* p) {
    uint2 r = *(const uint2*)p;
    float2 f0 = __half22float2(*(__half2*)&r.x);
    float2 f1 = __half22float2(*(__half2*)&r.y);
    return make_float4(f0.x, f0.y, f1.x, f1.y);
}

// ------------------- mix (fp16 inputs) -> fp16 out -------------------
__global__ void __launch_bounds__(256) mix_h_kernel(
        const __half* __restrict__ C0, const __half* __restrict__ C1, const __half* __restrict__ C2,
        const __half* __restrict__ S, __half* __restrict__ out16, int nrows) {
    int w = (int)((blockIdx.x * (unsigned)blockDim.x + threadIdx.x) >> 5);
    int lane = threadIdx.x & 31;
    if (w >= nrows) return;
    size_t base = (size_t)w * DIMV + lane * 4;
    float4 v = *(const float4*)(g_attvec + lane * 4);
    float4 c0 = ldh4(C0 + base);
    float4 c1 = ldh4(C1 + base);
    float4 c2 = ldh4(C2 + base);
    float w0 = c0.x * v.x + c0.y * v.y + c0.z * v.z + c0.w * v.w;
    float w1 = c1.x * v.x + c1.y * v.y + c1.z * v.z + c1.w * v.w;
    float w2 = c2.x * v.x + c2.y * v.y + c2.z * v.z + c2.w * v.w;
#pragma unroll
    for (int o = 16; o; o >>= 1) {
        w0 += __shfl_xor_sync(0xffffffffu, w0, o);
        w1 += __shfl_xor_sync(0xffffffffu, w1, o);
        w2 += __shfl_xor_sync(0xffffffffu, w2, o);
    }
    float m = fmaxf(w0, fmaxf(w1, w2));
    float e0 = expf(w0 - m), e1 = expf(w1 - m), e2 = expf(w2 - m);
    float inv = 1.f / (e0 + e1 + e2);
    e0 *= inv; e1 *= inv; e2 *= inv;
    float4 s = ldh4(S + base);
    float4 o;
    o.x = e0 * c0.x + e1 * c1.x + e2 * c2.x + 0.5f * s.x;
    o.y = e0 * c0.y + e1 * c1.y + e2 * c2.y + 0.5f * s.y;
    o.z = e0 * c0.z + e1 * c1.z + e2 * c2.z + 0.5f * s.z;
    o.w = e0 * c0.w + e1 * c1.w + e2 * c2.w + 0.5f * s.w;
    union { __half2 h[2]; uint2 u; } cv;
    cv.h[0] = __floats2half2_rn(o.x, o.y);
    cv.h[1] = __floats2half2_rn(o.z, o.w);
    *(uint2*)(out16 + base) = cv.u;
}

// ------------------- final mix -------------------
__global__ void __launch_bounds__(256) mix_final_kernel(
        const __half* __restrict__ gate16, const float* __restrict__ accc,
        const __half* __restrict__ n2, const float* __restrict__ sacc,
        const __half* __restrict__ s2n, float* __restrict__ out, int nrows) {
    int w = (int)((blockIdx.x * (unsigned)blockDim.x + threadIdx.x) >> 5);
    int lane = threadIdx.x & 31;
    if (w >= nrows) return;
    size_t base = (size_t)w * DIMV + lane * 4;
    float4 v = *(const float4*)(g_attvec + lane * 4);
    float4 c[3];
#pragma unroll
    for (int k = 0; k < 3; k++) {
        float4 g = ldh4(gate16 + (size_t)k * UF + base);
        float4 a = *(const float4*)(accc + (size_t)k * UF + base);
        float4 n = ldh4(n2 + (size_t)k * UF + base);
        c[k].x = g.x + a.x + n.x;
        c[k].y = g.y + a.y + n.y;
        c[k].z = g.z + a.z + n.z;
        c[k].w = g.w + a.w + n.w;
    }
    float w0 = c[0].x * v.x + c[0].y * v.y + c[0].z * v.z + c[0].w * v.w;
    float w1 = c[1].x * v.x + c[1].y * v.y + c[1].z * v.z + c[1].w * v.w;
    float w2 = c[2].x * v.x + c[2].y * v.y + c[2].z * v.z + c[2].w * v.w;
#pragma unroll
    for (int o = 16; o; o >>= 1) {
        w0 += __shfl_xor_sync(0xffffffffu, w0, o);
        w1 += __shfl_xor_sync(0xffffffffu, w1, o);
        w2 += __shfl_xor_sync(0xffffffffu, w2, o);
    }
    float m = fmaxf(w0, fmaxf(w1, w2));
    float e0 = expf(w0 - m), e1 = expf(w1 - m), e2 = expf(w2 - m);
    float inv = 1.f / (e0 + e1 + e2);
    e0 *= inv; e1 *= inv; e2 *= inv;
    float4 g3 = ldh4(gate16 + 3 * UF + base);
    float4 sa = *(const float4*)(sacc + base);
    float4 sn = ldh4(s2n + base);
    float4 o;
    o.x = e0 * c[0].x + e1 * c[1].x + e2 * c[2].x + 0.5f * (g3.x + sa.x + sn.x);
    o.y = e0 * c[0].y + e1 * c[1].y + e2 * c[2].y + 0.5f * (g3.y + sa.y + sn.y);
    o.z = e0 * c[0].z + e1 * c[1].z + e2 * c[2].z + 0.5f * (g3.z + sa.z + sn.z);
    o.w = e0 * c[0].w + e1 * c[1].w + e2 * c[2].w + 0.5f * (g3.w + sa.w + sn.w);
    *(float4*)(out + base) = o;
}

// ------------------- item output -------------------
__global__ void __launch_bounds__(256) item_out_kernel(const float* __restrict__ ie,
                                                       const float* __restrict__ ia,
                                                       const __half* __restrict__ i2n,
                                                       float* __restrict__ out) {
    int i = blockIdx.x * blockDim.x + threadIdx.x;
    if (i < (int)(IFl / 4)) {
        float4 a = __ldg((const float4*)ie + i);
        float4 b = *((const float4*)ia + i);
        float4 n = ldh4(i2n + (size_t)i * 4);
        a.x += b.x + n.x; a.y += b.y + n.y; a.z += b.z + n.z; a.w += b.w + n.w;
        *((float4*)out + i) = a;
    }
}

// ------------------- host orchestration -------------------
extern "C" void kernel_launch(void* const* d_in, const int* in_sizes, int n_in,
                              void* d_out, int out_size) {
    const float* u_emb = (const float*)d_in[0];
    const float* i_emb = (const float*)d_in[1];
    const float* gW = (const float*)d_in[2];
    const float* gB = (const float*)d_in[3];
    const float* att = (const float*)d_in[4];
    const float* attm = (const float*)d_in[5];
    const int* Hr[3] = {(const int*)d_in[6], (const int*)d_in[9], (const int*)d_in[12]};
    const int* Hc[3] = {(const int*)d_in[7], (const int*)d_in[10], (const int*)d_in[13]};
    const float* Hv[3] = {(const float*)d_in[8], (const float*)d_in[11], (const float*)d_in[14]};
    const int* Rr = (const int*)d_in[15];
    const int* Rc = (const int*)d_in[16];
    const float* Rv = (const float*)d_in[17];
    int EH = in_sizes[6], ER = in_sizes[15];
    float* out = (float*)d_out;

    static float* B = nullptr;
    static __half* H = nullptr;
    static int *cnt = nullptr, *cur = nullptr, *offs = nullptr, *aux = nullptr;
    static int2* pair = nullptr;
    static cudaStream_t s2 = nullptr;
    static cudaEvent_t evFork = nullptr, evJoin = nullptr;
    if (!B) {
        cudaGetSymbolAddress((void**)&B, g_buf);
        cudaGetSymbolAddress((void**)&H, g_hbuf);
        cudaGetSymbolAddress((void**)&cnt, g_cnt);
        cudaGetSymbolAddress((void**)&cur, g_cur);
        cudaGetSymbolAddress((void**)&offs, g_offs);
        cudaGetSymbolAddress((void**)&pair, g_pair);
        cudaGetSymbolAddress((void**)&aux, g_aux);
        cudaFuncSetAttribute(gate_mma_kernel, cudaFuncAttributeMaxDynamicSharedMemorySize, GATE_SMEM);
        cudaStreamCreateWithFlags(&s2, cudaStreamNonBlocking);
        cudaEventCreateWithFlags(&evFork, cudaEventDisableTiming);
        cudaEventCreateWithFlags(&evJoin, cudaEventDisableTiming);
    }
    float* accc = B + O_ACCC;
    float* sacc = B + O_SACC;
    float* iacc = B + O_IACC;
    __half* gate16 = H + H_GATE;
    __half* curA16 = H + H_CURA;
    __half* mix16 = H + H_MIX;
    __half* s1_16 = H + H_S1;
    __half* n2_16 = H + H_N2;
    __half* s2n16 = H + H_S2N;
    __half* i1_16 = H + H_I1;
    __half* i2n16 = H + H_I2N;
    __half* iemb16 = H + H_IEMB;

#define GP16(c) (gate16 + (size_t)(c) * UF)
#define CA16(c) (curA16 + (size_t)(c) * UF)
#define AC(c) (accc + (size_t)(c) * UF)
#define N2(c) (n2_16 + (size_t)(c) * UF)

    Build5 bj;
    for (int k = 0; k < 3; k++)
        bj.j[k] = {Hr[k], Hc[k], Hv[k], cnt + k * NU, cur + k * NU, offs + k * OSTR,
                   pair + (size_t)k * EHMAX, EH, NU};
    bj.j[3] = {Rr, Rc, Rv, cnt + 3 * NU, cur + 3 * NU, offs + 3 * OSTR,
               pair + 3 * (size_t)EHMAX, ER, NU};
    bj.j[4] = {Rc, Rr, Rv, cnt + 4 * NU, cur + 4 * NU, offs + 4 * OSTR,
               pair + 3 * (size_t)EHMAX + ERMAX, ER, NI};
    {
        int be[5];
        for (int k = 0; k < 5; k++) be[k] = (bj.j[k].ne + 255) / 256;
        bj.bstart[0] = 0;
        for (int k = 0; k < 5; k++) bj.bstart[k + 1] = bj.bstart[k] + be[k];
    }

    const int* offsR = bj.j[3].offs;  const int2* pairR = bj.j[3].pair;
    const int* offsRT = bj.j[4].offs; const int2* pairRT = bj.j[4].pair;

    // ---- fork: CSR build on s2, dense prologue on main ----
    cudaEventRecord(evFork, 0);
    cudaStreamWaitEvent(s2, evFork, 0);

    cudaMemsetAsync(cnt, 0, CNT_TOT * sizeof(int), s2);
    count_kernel<<<bj.bstart[5], 256, 0, s2>>>(bj);
    scan_chunks_kernel<<<dim3(NCHU, 5), 256, 0, s2>>>(bj, aux);
    scan_aux_kernel<<<1, 160, 0, s2>>>(bj, aux);
    scan_apply_kernel<<<dim3(NCHU, 5), 256, 0, s2>>>(bj, aux);
    scatter_kernel<<<bj.bstart[5], 256, 0, s2>>>(bj);
    cudaEventRecord(evJoin, s2);

    attvec_kernel<<<1, 128>>>(att, attm);
    f2h_kernel<<<(int)((IFl / 4 + 255) / 256), 256>>>(i_emb, iemb16, (int)(IFl / 4));
    gate_mma_kernel<<<dim3(148, 4), 256, GATE_SMEM>>>(u_emb, gW, gB, gate16);

    int mixb = (NU + 7) / 8;
    const int BU = (NU + 7) / 8;
    const int BI = (NI + 7) / 8;

    // layer-1 mix: fp16 gates, S = gate channel 3
    mix_h_kernel<<<mixb, 256>>>(GP16(0), GP16(1), GP16(2), GP16(3), mix16, NU);

    cudaStreamWaitEvent(0, evJoin, 0);   // join before SpMM

    // ---------------- layer 1: raw fp16 out + fp32 l2norm write ----------------
    {
        Csr5 a;
        for (int k = 0; k < 3; k++)
            a.j[k] = {bj.j[k].offs, bj.j[k].pair, GP16(k), CA16(k), AC(k), nullptr, NU};
        a.j[3] = {offsRT, pairRT, mix16, i1_16, iacc, nullptr, NI};  // item1 = R^T @ mixed
        a.j[4] = {offsR, pairR, iemb16, s1_16, sacc, nullptr, NU};   // s1 = R @ i_emb
        a.bstart[0] = 0; a.bstart[1] = BU; a.bstart[2] = 2 * BU; a.bstart[3] = 3 * BU;
        a.bstart[4] = 3 * BU + BI; a.bstart[5] = 4 * BU + BI;
        spmm_csr5_kernel<<<a.bstart[5], 256>>>(a);
    }

    // ---------------- layer 2: l2norm fp16 write only ----------------
    mix_h_kernel<<<mixb, 256>>>(CA16(0), CA16(1), CA16(2), s1_16, mix16, NU);
    {
        Csr5 a;
        for (int k = 0; k < 3; k++)
            a.j[k] = {bj.j[k].offs, bj.j[k].pair, CA16(k), nullptr, nullptr, N2(k), NU};
        a.j[3] = {offsRT, pairRT, mix16, nullptr, nullptr, i2n16, NI};  // l2n(R^T @ mixed2)
        a.j[4] = {offsR, pairR, i1_16, nullptr, nullptr, s2n16, NU};    // l2n(R @ item1)
        a.bstart[0] = 0; a.bstart[1] = BU; a.bstart[2] = 2 * BU; a.bstart[3] = 3 * BU;
        a.bstart[4] = 3 * BU + BI; a.bstart[5] = 4 * BU + BI;
        spmm_csr5_kernel<<<a.bstart[5], 256>>>(a);
    }

    // ---------------- final ----------------
    mix_final_kernel<<<mixb, 256>>>(gate16, accc, n2_16, sacc, s2n16, out, NU);
    item_out_kernel<<<(int)((IFl / 4 + 255) / 256), 256>>>(i_emb, iacc, i2n16,
                                                           out + (size_t)NU * DIMV);
}

// round 14
// speedup vs baseline: 1.7715x; 1.0347x over previous
#include <cuda_runtime.h>
#include <cuda_fp16.h>
#include <mma.h>
#include <cstdint>

using namespace nvcuda;

#define NU 50000
#define NI 25000
#define DIMV 128
#define EHMAX 600000
#define ERMAX 1000000
#define CHUNK 1024
#define NCHU 49
#define OSTR 50016

#define UF ((size_t)NU * DIMV)
#define IFl ((size_t)NI * DIMV)

// ------------------- fp32 scratch: layer-1 norms only -------------------
#define O_ACCC ((size_t)0)
#define O_SACC (3 * UF)
#define O_IACC (4 * UF)
#define TOTALF (4 * UF + IFl)
__device__ __align__(16) float g_buf[TOTALF];

// ------------------- fp16 scratch -------------------
#define H_GATE ((size_t)0)          // 4 channels
#define H_CURA (4 * UF)             // 3 channels, layer-1 H outputs (raw)
#define H_MIX  (7 * UF)
#define H_S1   (8 * UF)
#define H_N2   (9 * UF)             // 3 channels, l2n(layer-2 H outputs)
#define H_S2N  (12 * UF)            // l2n(layer-2 R output)
#define H_I1   (13 * UF)
#define H_I2N  (13 * UF + IFl)      // l2n(layer-2 RT output)
#define H_IEMB (13 * UF + 2 * IFl)
#define TOTALH (13 * UF + 3 * IFl)
__device__ __align__(16) __half g_hbuf[TOTALH];

__device__ float g_attvec[DIMV];

// ------------------- CSR scratch -------------------
#define CNT_TOT (4 * NU + NI)
#define OFFS_TOT (4 * OSTR + NI + 16)
#define PE_TOT (3 * EHMAX + 2 * ERMAX)
__device__ __align__(16) int g_cnt[CNT_TOT];
__device__ __align__(16) int g_cur[CNT_TOT];
__device__ __align__(16) int g_offs[OFFS_TOT];
__device__ __align__(16) int2 g_pair[PE_TOT];
__device__ int g_aux[5 * 64];

// ------------------- attention vector: v = M @ a -------------------
__global__ void attvec_kernel(const float* __restrict__ att, const float* __restrict__ mat) {
    int j = threadIdx.x;
    float s = 0.f;
#pragma unroll 8
    for (int d = 0; d < DIMV; d++) s += mat[j * DIMV + d] * att[d];
    g_attvec[j] = s;
}

// ------------------- f32 -> f16 conversion -------------------
__global__ void __launch_bounds__(256) f2h_kernel(const float* __restrict__ src,
                                                  __half* __restrict__ dst, int n4) {
    int i = blockIdx.x * 256 + threadIdx.x;
    if (i < n4) {
        float4 v = __ldg((const float4*)src + i);
        union { __half2 h[2]; uint2 u; } cv;
        cv.h[0] = __floats2half2_rn(v.x, v.y);
        cv.h[1] = __floats2half2_rn(v.z, v.w);
        *(uint2*)(dst + (size_t)i * 4) = cv.u;
    }
}

// ------------------- gating via tensor-core HMMA -------------------
#define GLDM 136
#define SLDM 136
#define SM_W 0
#define SM_U (128 * GLDM)
#define SM_S_BYTES (2 * 128 * GLDM * 2)
#define GATE_SMEM (SM_S_BYTES + 128 * SLDM * 4)

__global__ void __launch_bounds__(256) gate_mma_kernel(const float* __restrict__ U,
                                                       const float* __restrict__ W4,
                                                       const float* __restrict__ B4,
                                                       __half* __restrict__ gate16) {
    extern __shared__ __half smh[];
    __half* Wsh = smh + SM_W;
    __half* Ush = smh + SM_U;
    float* St = (float*)((char*)smh + SM_S_BYTES);
    int tid = threadIdx.x;
    int warp = tid >> 5;
    int c = blockIdx.y;
    const float* W = W4 + c * DIMV * DIMV;
    __half* out16 = gate16 + (size_t)c * UF;

    for (int i = tid; i < DIMV * DIMV; i += 256) {
        int k = i >> 7, n = i & 127;
        Wsh[k * GLDM + n] = __float2half_rn(W[i]);
    }
    int ncol = tid & 127;
    float bias = B4[c * DIMV + ncol];

    for (int tile = blockIdx.x * 128; tile < NU; tile += gridDim.x * 128) {
        __syncthreads();
        for (int i = tid; i < 128 * DIMV; i += 256) {
            int r = i >> 7, n = i & 127;
            int gr = tile + r;
            float v = (gr < NU) ? U[(size_t)gr * DIMV + n] : 0.f;
            Ush[r * GLDM + n] = __float2half_rn(v);
        }
        __syncthreads();
        {
            wmma::fragment<wmma::accumulator, 16, 16, 16, float> fc[8];
#pragma unroll
            for (int n0 = 0; n0 < 8; n0++) wmma::fill_fragment(fc[n0], 0.f);
#pragma unroll
            for (int k0 = 0; k0 < 8; k0++) {
                wmma::fragment<wmma::matrix_a, 16, 16, 16, __half, wmma::row_major> fa;
                wmma::load_matrix_sync(fa, Ush + (warp * 16) * GLDM + k0 * 16, GLDM);
#pragma unroll
                for (int n0 = 0; n0 < 8; n0++) {
                    wmma::fragment<wmma::matrix_b, 16, 16, 16, __half, wmma::row_major> fb;
                    wmma::load_matrix_sync(fb, Wsh + (k0 * 16) * GLDM + n0 * 16, GLDM);
                    wmma::mma_sync(fc[n0], fa, fb, fc[n0]);
                }
            }
#pragma unroll
            for (int n0 = 0; n0 < 8; n0++)
                wmma::store_matrix_sync(St + (warp * 16) * SLDM + n0 * 16, fc[n0],
                                        SLDM, wmma::mem_row_major);
        }
        __syncthreads();
        for (int i = tid; i < 128 * DIMV; i += 256) {
            int r = i >> 7;
            int gr = tile + r;
            if (gr < NU) {
                float a = St[r * SLDM + ncol] + bias;
                float u = __half2float(Ush[r * GLDM + ncol]);
                out16[(size_t)gr * DIMV + ncol] = __float2half_rn(u / (1.f + expf(-a)));
            }
        }
    }
}

// ------------------- CSR build -------------------
struct BuildJob { const int* rows; const int* cols; const float* vals;
                  int* cnt; int* cur; int* offs; int2* pair; int ne; int nrows; };
struct Build5 { BuildJob j[5]; int bstart[6]; };

__device__ __forceinline__ int build_job_of(const Build5& a, int blk) {
    int k = 0;
#pragma unroll
    for (int q = 1; q < 5; q++) if (blk >= a.bstart[q]) k = q;
    return k;
}

__global__ void __launch_bounds__(256) count_kernel(Build5 a) {
    int k = build_job_of(a, blockIdx.x);
    BuildJob jb = a.j[k];
    int e = (blockIdx.x - a.bstart[k]) * 256 + threadIdx.x;
    if (e < jb.ne) atomicAdd(jb.cnt + __ldg(jb.rows + e), 1);
}

__global__ void __launch_bounds__(256) scan_chunks_kernel(Build5 a, int* __restrict__ aux) {
    BuildJob jb = a.j[blockIdx.y];
    int n = jb.nrows;
    int base = blockIdx.x * CHUNK;
    if (base >= n) return;
    int tid = threadIdx.x;
    int lane = tid & 31, wid = tid >> 5;
    int i = base + tid * 4;
    int4 v = make_int4(0, 0, 0, 0);
    if (i < n) v = *(const int4*)(jb.cnt + i);
    int s = v.x + v.y + v.z + v.w;
    int ss = s;
#pragma unroll
    for (int o = 1; o < 32; o <<= 1) { int tt = __shfl_up_sync(0xffffffffu, ss, o); if (lane >= o) ss += tt; }
    __shared__ int wsum[8];
    if (lane == 31) wsum[wid] = ss;
    __syncthreads();
    if (tid < 8) {
        int w = wsum[tid];
#pragma unroll
        for (int o = 1; o < 8; o <<= 1) { int tt = __shfl_up_sync(0xffu, w, o); if (tid >= o) w += tt; }
        wsum[tid] = w;
    }
    __syncthreads();
    int excl = ss - s + (wid ? wsum[wid - 1] : 0);
    if (i < n) {
        int4 e;
        e.x = excl; e.y = excl + v.x; e.z = e.y + v.y; e.w = e.z + v.z;
        *(int4*)(jb.offs + i) = e;
    }
    if (tid == 255) aux[blockIdx.y * 64 + blockIdx.x] = wsum[7];
}

__global__ void __launch_bounds__(160) scan_aux_kernel(Build5 a, int* __restrict__ aux) {
    int wid = threadIdx.x >> 5;
    if (wid >= 5) return;
    BuildJob jb = a.j[wid];
    int nch = (jb.nrows + CHUNK - 1) / CHUNK;
    int lane = threadIdx.x & 31;
    int carry = 0;
    for (int b0 = 0; b0 < nch; b0 += 32) {
        int idx = b0 + lane;
        int v = (idx < nch) ? aux[wid * 64 + idx] : 0;
        int s = v;
#pragma unroll
        for (int o = 1; o < 32; o <<= 1) { int tt = __shfl_up_sync(0xffffffffu, s, o); if (lane >= o) s += tt; }
        if (idx < nch) aux[wid * 64 + idx] = carry + s - v;
        carry += __shfl_sync(0xffffffffu, s, 31);
    }
    if (lane == 0) jb.offs[jb.nrows] = carry;
}

__global__ void __launch_bounds__(256) scan_apply_kernel(Build5 a, const int* __restrict__ aux) {
    BuildJob jb = a.j[blockIdx.y];
    int n = jb.nrows;
    int base = blockIdx.x * CHUNK;
    if (base >= n) return;
    int add = aux[blockIdx.y * 64 + blockIdx.x];
    int i = base + threadIdx.x * 4;
    if (i < n) {
        int4 e = *(const int4*)(jb.offs + i);
        e.x += add; e.y += add; e.z += add; e.w += add;
        *(int4*)(jb.offs + i) = e;
        *(int4*)(jb.cur + i) = e;
    }
}

__global__ void __launch_bounds__(256) scatter_kernel(Build5 a) {
    int k = build_job_of(a, blockIdx.x);
    BuildJob jb = a.j[k];
    int e = (blockIdx.x - a.bstart[k]) * 256 + threadIdx.x;
    if (e >= jb.ne) return;
    int r = __ldg(jb.rows + e);
    int p = atomicAdd(jb.cur + r, 1);
    jb.pair[p] = make_int2(__ldg(jb.cols + e), __float_as_int(__ldg(jb.vals + e)));
}

// ------------------- CSR SpMM (fp16 gathers), half-warp per row -------------------
// 16 lanes per row, LDG.128 gathers (16 x 16B = 256 B/edge), warp covers 2 rows.
struct CsrJob { const int* offs; const int2* pair; const __half* X;
                __half* Y16; float* acc; __half* Yn16; int nrows; };
struct Csr5 { CsrJob j[5]; int bstart[6]; };

__device__ __forceinline__ void fma_h8(float* acc, float v, uint4 raw) {
    float2 f0 = __half22float2(*(__half2*)&raw.x);
    float2 f1 = __half22float2(*(__half2*)&raw.y);
    float2 f2 = __half22float2(*(__half2*)&raw.z);
    float2 f3 = __half22float2(*(__half2*)&raw.w);
    acc[0] += v * f0.x; acc[1] += v * f0.y;
    acc[2] += v * f1.x; acc[3] += v * f1.y;
    acc[4] += v * f2.x; acc[5] += v * f2.y;
    acc[6] += v * f3.x; acc[7] += v * f3.y;
}

__global__ void __launch_bounds__(256) spmm_csr5_kernel(Csr5 a) {
    int blk = blockIdx.x;
    int k = 0;
#pragma unroll
    for (int q = 1; q < 5; q++) if (blk >= a.bstart[q]) k = q;
    CsrJob jb = a.j[k];
    int lane = threadIdx.x & 31;
    int hl = lane & 15;              // lane within half-warp
    int side = lane >> 4;
    int warp = threadIdx.x >> 5;
    int w = (blk - a.bstart[k]) * 16 + warp * 2 + side;
    unsigned hmask = 0xFFFFu << (side * 16);
    if (w >= jb.nrows) return;
    int start = __ldg(jb.offs + w);
    int end = __ldg(jb.offs + w + 1);
    float acc[8];
#pragma unroll
    for (int q = 0; q < 8; q++) acc[q] = 0.f;
    const __half* X = jb.X;
    for (int b = start; b < end; b += 16) {
        int i = b + hl;
        int c = 0; float v = 0.f;
        if (i < end) { int2 pr = __ldg(jb.pair + i); c = pr.x; v = __int_as_float(pr.y); }
        int m = end - b; if (m > 16) m = 16;
        int j = 0;
        for (; j + 4 <= m; j += 4) {
            int c0 = __shfl_sync(hmask, c, j + 0, 16);
            int c1 = __shfl_sync(hmask, c, j + 1, 16);
            int c2 = __shfl_sync(hmask, c, j + 2, 16);
            int c3 = __shfl_sync(hmask, c, j + 3, 16);
            uint4 x0 = __ldg((const uint4*)(X + (size_t)c0 * DIMV) + hl);
            uint4 x1 = __ldg((const uint4*)(X + (size_t)c1 * DIMV) + hl);
            uint4 x2 = __ldg((const uint4*)(X + (size_t)c2 * DIMV) + hl);
            uint4 x3 = __ldg((const uint4*)(X + (size_t)c3 * DIMV) + hl);
            float v0 = __shfl_sync(hmask, v, j + 0, 16);
            float v1 = __shfl_sync(hmask, v, j + 1, 16);
            float v2 = __shfl_sync(hmask, v, j + 2, 16);
            float v3 = __shfl_sync(hmask, v, j + 3, 16);
            fma_h8(acc, v0, x0);
            fma_h8(acc, v1, x1);
            fma_h8(acc, v2, x2);
            fma_h8(acc, v3, x3);
        }
        for (; j < m; j++) {
            int cj = __shfl_sync(hmask, c, j, 16);
            float vj = __shfl_sync(hmask, v, j, 16);
            uint4 x = __ldg((const uint4*)(X + (size_t)cj * DIMV) + hl);
            fma_h8(acc, vj, x);
        }
    }
    size_t base = (size_t)w * DIMV + hl * 8;
    if (jb.Y16) {
        union { __half2 h[4]; uint4 u; } cv;
        cv.h[0] = __floats2half2_rn(acc[0], acc[1]);
        cv.h[1] = __floats2half2_rn(acc[2], acc[3]);
        cv.h[2] = __floats2half2_rn(acc[4], acc[5]);
        cv.h[3] = __floats2half2_rn(acc[6], acc[7]);
        *(uint4*)(jb.Y16 + base) = cv.u;
    }
    if (jb.acc || jb.Yn16) {
        float ss = 0.f;
#pragma unroll
        for (int q = 0; q < 8; q++) ss += acc[q] * acc[q];
#pragma unroll
        for (int o = 8; o; o >>= 1) ss += __shfl_xor_sync(hmask, ss, o, 16);
        float sc = rsqrtf(fmaxf(ss, 1e-12f));
        if (jb.acc) {
            float4 a0 = make_float4(acc[0] * sc, acc[1] * sc, acc[2] * sc, acc[3] * sc);
            float4 a1 = make_float4(acc[4] * sc, acc[5] * sc, acc[6] * sc, acc[7] * sc);
            *(float4*)(jb.acc + base) = a0;
            *(float4*)(jb.acc + base + 4) = a1;
        }
        if (jb.Yn16) {
            union { __half2 h[4]; uint4 u; } cv;
            cv.h[0] = __floats2half2_rn(acc[0] * sc, acc[1] * sc);
            cv.h[1] = __floats2half2_rn(acc[2] * sc, acc[3] * sc);
            cv.h[2] = __floats2half2_rn(acc[4] * sc, acc[5] * sc);
            cv.h[3] = __floats2half2_rn(acc[6] * sc, acc[7] * sc);
            *(uint4*)(jb.Yn16 + base) = cv.u;
        }
    }
}

// ------------------- helpers -------------------
__device__ __forceinline__ float4 ldh4(const __half* p) {
    uint2 r = *(const uint2*)p;
    float2 f0 = __half22float2(*(__half2*)&r.x);
    float2 f1 = __half22float2(*(__half2*)&r.y);
    return make_float4(f0.x, f0.y, f1.x, f1.y);
}

// ------------------- mix (fp16 inputs) -> fp16 out -------------------
__global__ void __launch_bounds__(256) mix_h_kernel(
        const __half* __restrict__ C0, const __half* __restrict__ C1, const __half* __restrict__ C2,
        const __half* __restrict__ S, __half* __restrict__ out16, int nrows) {
    int w = (int)((blockIdx.x * (unsigned)blockDim.x + threadIdx.x) >> 5);
    int lane = threadIdx.x & 31;
    if (w >= nrows) return;
    size_t base = (size_t)w * DIMV + lane * 4;
    float4 v = *(const float4*)(g_attvec + lane * 4);
    float4 c0 = ldh4(C0 + base);
    float4 c1 = ldh4(C1 + base);
    float4 c2 = ldh4(C2 + base);
    float w0 = c0.x * v.x + c0.y * v.y + c0.z * v.z + c0.w * v.w;
    float w1 = c1.x * v.x + c1.y * v.y + c1.z * v.z + c1.w * v.w;
    float w2 = c2.x * v.x + c2.y * v.y + c2.z * v.z + c2.w * v.w;
#pragma unroll
    for (int o = 16; o; o >>= 1) {
        w0 += __shfl_xor_sync(0xffffffffu, w0, o);
        w1 += __shfl_xor_sync(0xffffffffu, w1, o);
        w2 += __shfl_xor_sync(0xffffffffu, w2, o);
    }
    float m = fmaxf(w0, fmaxf(w1, w2));
    float e0 = expf(w0 - m), e1 = expf(w1 - m), e2 = expf(w2 - m);
    float inv = 1.f / (e0 + e1 + e2);
    e0 *= inv; e1 *= inv; e2 *= inv;
    float4 s = ldh4(S + base);
    float4 o;
    o.x = e0 * c0.x + e1 * c1.x + e2 * c2.x + 0.5f * s.x;
    o.y = e0 * c0.y + e1 * c1.y + e2 * c2.y + 0.5f * s.y;
    o.z = e0 * c0.z + e1 * c1.z + e2 * c2.z + 0.5f * s.z;
    o.w = e0 * c0.w + e1 * c1.w + e2 * c2.w + 0.5f * s.w;
    union { __half2 h[2]; uint2 u; } cv;
    cv.h[0] = __floats2half2_rn(o.x, o.y);
    cv.h[1] = __floats2half2_rn(o.z, o.w);
    *(uint2*)(out16 + base) = cv.u;
}

// ------------------- final mix -------------------
__global__ void __launch_bounds__(256) mix_final_kernel(
        const __half* __restrict__ gate16, const float* __restrict__ accc,
        const __half* __restrict__ n2, const float* __restrict__ sacc,
        const __half* __restrict__ s2n, float* __restrict__ out, int nrows) {
    int w = (int)((blockIdx.x * (unsigned)blockDim.x + threadIdx.x) >> 5);
    int lane = threadIdx.x & 31;
    if (w >= nrows) return;
    size_t base = (size_t)w * DIMV + lane * 4;
    float4 v = *(const float4*)(g_attvec + lane * 4);
    float4 c[3];
#pragma unroll
    for (int k = 0; k < 3; k++) {
        float4 g = ldh4(gate16 + (size_t)k * UF + base);
        float4 a = *(const float4*)(accc + (size_t)k * UF + base);
        float4 n = ldh4(n2 + (size_t)k * UF + base);
        c[k].x = g.x + a.x + n.x;
        c[k].y = g.y + a.y + n.y;
        c[k].z = g.z + a.z + n.z;
        c[k].w = g.w + a.w + n.w;
    }
    float w0 = c[0].x * v.x + c[0].y * v.y + c[0].z * v.z + c[0].w * v.w;
    float w1 = c[1].x * v.x + c[1].y * v.y + c[1].z * v.z + c[1].w * v.w;
    float w2 = c[2].x * v.x + c[2].y * v.y + c[2].z * v.z + c[2].w * v.w;
#pragma unroll
    for (int o = 16; o; o >>= 1) {
        w0 += __shfl_xor_sync(0xffffffffu, w0, o);
        w1 += __shfl_xor_sync(0xffffffffu, w1, o);
        w2 += __shfl_xor_sync(0xffffffffu, w2, o);
    }
    float m = fmaxf(w0, fmaxf(w1, w2));
    float e0 = expf(w0 - m), e1 = expf(w1 - m), e2 = expf(w2 - m);
    float inv = 1.f / (e0 + e1 + e2);
    e0 *= inv; e1 *= inv; e2 *= inv;
    float4 g3 = ldh4(gate16 + 3 * UF + base);
    float4 sa = *(const float4*)(sacc + base);
    float4 sn = ldh4(s2n + base);
    float4 o;
    o.x = e0 * c[0].x + e1 * c[1].x + e2 * c[2].x + 0.5f * (g3.x + sa.x + sn.x);
    o.y = e0 * c[0].y + e1 * c[1].y + e2 * c[2].y + 0.5f * (g3.y + sa.y + sn.y);
    o.z = e0 * c[0].z + e1 * c[1].z + e2 * c[2].z + 0.5f * (g3.z + sa.z + sn.z);
    o.w = e0 * c[0].w + e1 * c[1].w + e2 * c[2].w + 0.5f * (g3.w + sa.w + sn.w);
    *(float4*)(out + base) = o;
}

// ------------------- item output -------------------
__global__ void __launch_bounds__(256) item_out_kernel(const float* __restrict__ ie,
                                                       const float* __restrict__ ia,
                                                       const __half* __restrict__ i2n,
                                                       float* __restrict__ out) {
    int i = blockIdx.x * blockDim.x + threadIdx.x;
    if (i < (int)(IFl / 4)) {
        float4 a = __ldg((const float4*)ie + i);
        float4 b = *((const float4*)ia + i);
        float4 n = ldh4(i2n + (size_t)i * 4);
        a.x += b.x + n.x; a.y += b.y + n.y; a.z += b.z + n.z; a.w += b.w + n.w;
        *((float4*)out + i) = a;
    }
}

// ------------------- host orchestration -------------------
extern "C" void kernel_launch(void* const* d_in, const int* in_sizes, int n_in,
                              void* d_out, int out_size) {
    const float* u_emb = (const float*)d_in[0];
    const float* i_emb = (const float*)d_in[1];
    const float* gW = (const float*)d_in[2];
    const float* gB = (const float*)d_in[3];
    const float* att = (const float*)d_in[4];
    const float* attm = (const float*)d_in[5];
    const int* Hr[3] = {(const int*)d_in[6], (const int*)d_in[9], (const int*)d_in[12]};
    const int* Hc[3] = {(const int*)d_in[7], (const int*)d_in[10], (const int*)d_in[13]};
    const float* Hv[3] = {(const float*)d_in[8], (const float*)d_in[11], (const float*)d_in[14]};
    const int* Rr = (const int*)d_in[15];
    const int* Rc = (const int*)d_in[16];
    const float* Rv = (const float*)d_in[17];
    int EH = in_sizes[6], ER = in_sizes[15];
    float* out = (float*)d_out;

    static float* B = nullptr;
    static __half* H = nullptr;
    static int *cnt = nullptr, *cur = nullptr, *offs = nullptr, *aux = nullptr;
    static int2* pair = nullptr;
    static cudaStream_t s2 = nullptr;
    static cudaEvent_t evFork = nullptr, evJoin = nullptr;
    if (!B) {
        cudaGetSymbolAddress((void**)&B, g_buf);
        cudaGetSymbolAddress((void**)&H, g_hbuf);
        cudaGetSymbolAddress((void**)&cnt, g_cnt);
        cudaGetSymbolAddress((void**)&cur, g_cur);
        cudaGetSymbolAddress((void**)&offs, g_offs);
        cudaGetSymbolAddress((void**)&pair, g_pair);
        cudaGetSymbolAddress((void**)&aux, g_aux);
        cudaFuncSetAttribute(gate_mma_kernel, cudaFuncAttributeMaxDynamicSharedMemorySize, GATE_SMEM);
        cudaStreamCreateWithFlags(&s2, cudaStreamNonBlocking);
        cudaEventCreateWithFlags(&evFork, cudaEventDisableTiming);
        cudaEventCreateWithFlags(&evJoin, cudaEventDisableTiming);
    }
    float* accc = B + O_ACCC;
    float* sacc = B + O_SACC;
    float* iacc = B + O_IACC;
    __half* gate16 = H + H_GATE;
    __half* curA16 = H + H_CURA;
    __half* mix16 = H + H_MIX;
    __half* s1_16 = H + H_S1;
    __half* n2_16 = H + H_N2;
    __half* s2n16 = H + H_S2N;
    __half* i1_16 = H + H_I1;
    __half* i2n16 = H + H_I2N;
    __half* iemb16 = H + H_IEMB;

#define GP16(c) (gate16 + (size_t)(c) * UF)
#define CA16(c) (curA16 + (size_t)(c) * UF)
#define AC(c) (accc + (size_t)(c) * UF)
#define N2(c) (n2_16 + (size_t)(c) * UF)

    Build5 bj;
    for (int k = 0; k < 3; k++)
        bj.j[k] = {Hr[k], Hc[k], Hv[k], cnt + k * NU, cur + k * NU, offs + k * OSTR,
                   pair + (size_t)k * EHMAX, EH, NU};
    bj.j[3] = {Rr, Rc, Rv, cnt + 3 * NU, cur + 3 * NU, offs + 3 * OSTR,
               pair + 3 * (size_t)EHMAX, ER, NU};
    bj.j[4] = {Rc, Rr, Rv, cnt + 4 * NU, cur + 4 * NU, offs + 4 * OSTR,
               pair + 3 * (size_t)EHMAX + ERMAX, ER, NI};
    {
        int be[5];
        for (int k = 0; k < 5; k++) be[k] = (bj.j[k].ne + 255) / 256;
        bj.bstart[0] = 0;
        for (int k = 0; k < 5; k++) bj.bstart[k + 1] = bj.bstart[k] + be[k];
    }

    const int* offsR = bj.j[3].offs;  const int2* pairR = bj.j[3].pair;
    const int* offsRT = bj.j[4].offs; const int2* pairRT = bj.j[4].pair;

    // ---- fork: CSR build on s2, dense prologue on main ----
    cudaEventRecord(evFork, 0);
    cudaStreamWaitEvent(s2, evFork, 0);

    cudaMemsetAsync(cnt, 0, CNT_TOT * sizeof(int), s2);
    count_kernel<<<bj.bstart[5], 256, 0, s2>>>(bj);
    scan_chunks_kernel<<<dim3(NCHU, 5), 256, 0, s2>>>(bj, aux);
    scan_aux_kernel<<<1, 160, 0, s2>>>(bj, aux);
    scan_apply_kernel<<<dim3(NCHU, 5), 256, 0, s2>>>(bj, aux);
    scatter_kernel<<<bj.bstart[5], 256, 0, s2>>>(bj);
    cudaEventRecord(evJoin, s2);

    attvec_kernel<<<1, 128>>>(att, attm);
    f2h_kernel<<<(int)((IFl / 4 + 255) / 256), 256>>>(i_emb, iemb16, (int)(IFl / 4));
    gate_mma_kernel<<<dim3(148, 4), 256, GATE_SMEM>>>(u_emb, gW, gB, gate16);

    int mixb = (NU + 7) / 8;
    const int BU = (NU + 15) / 16;   // 16 rows per block (2 per warp)
    const int BI = (NI + 15) / 16;

    // layer-1 mix: fp16 gates, S = gate channel 3
    mix_h_kernel<<<mixb, 256>>>(GP16(0), GP16(1), GP16(2), GP16(3), mix16, NU);

    cudaStreamWaitEvent(0, evJoin, 0);   // join before SpMM

    // ---------------- layer 1: raw fp16 out + fp32 l2norm write ----------------
    {
        Csr5 a;
        for (int k = 0; k < 3; k++)
            a.j[k] = {bj.j[k].offs, bj.j[k].pair, GP16(k), CA16(k), AC(k), nullptr, NU};
        a.j[3] = {offsRT, pairRT, mix16, i1_16, iacc, nullptr, NI};  // item1 = R^T @ mixed
        a.j[4] = {offsR, pairR, iemb16, s1_16, sacc, nullptr, NU};   // s1 = R @ i_emb
        a.bstart[0] = 0; a.bstart[1] = BU; a.bstart[2] = 2 * BU; a.bstart[3] = 3 * BU;
        a.bstart[4] = 3 * BU + BI; a.bstart[5] = 4 * BU + BI;
        spmm_csr5_kernel<<<a.bstart[5], 256>>>(a);
    }

    // ---------------- layer 2: l2norm fp16 write only ----------------
    mix_h_kernel<<<mixb, 256>>>(CA16(0), CA16(1), CA16(2), s1_16, mix16, NU);
    {
        Csr5 a;
        for (int k = 0; k < 3; k++)
            a.j[k] = {bj.j[k].offs, bj.j[k].pair, CA16(k), nullptr, nullptr, N2(k), NU};
        a.j[3] = {offsRT, pairRT, mix16, nullptr, nullptr, i2n16, NI};  // l2n(R^T @ mixed2)
        a.j[4] = {offsR, pairR, i1_16, nullptr, nullptr, s2n16, NU};    // l2n(R @ item1)
        a.bstart[0] = 0; a.bstart[1] = BU; a.bstart[2] = 2 * BU; a.bstart[3] = 3 * BU;
        a.bstart[4] = 3 * BU + BI; a.bstart[5] = 4 * BU + BI;
        spmm_csr5_kernel<<<a.bstart[5], 256>>>(a);
    }

    // ---------------- final ----------------
    mix_final_kernel<<<mixb, 256>>>(gate16, accc, n2_16, sacc, s2n16, out, NU);
    item_out_kernel<<<(int)((IFl / 4 + 255) / 256), 256>>>(i_emb, iacc, i2n16,
                                                           out + (size_t)NU * DIMV);
}